// round 5
// baseline (speedup 1.0000x reference)
#include <cuda_runtime.h>
#include <cuda_bf16.h>
#include <cstdint>
#include <math.h>

// ---------------------------------------------------------------------------
// Problem constants
// ---------------------------------------------------------------------------
#define B_ 4
#define L_ 2048
#define D_ 256
#define H_ 4096
#define M_ (B_ * L_)          // 8192
#define CHUNK_ 128
#define NC_ (L_ / CHUNK_)     // 16

// ---------------------------------------------------------------------------
// Scratch (device globals; no allocation allowed)
// g_b holds b [M,H] fp32 for the scan; dead after phaseC, so GEMM2's split-K
// partials (2 x M x D fp32) reuse its space.
// ---------------------------------------------------------------------------
__device__ __align__(256) float         g_b[(size_t)M_ * H_];      // 128 MB
__device__ __align__(256) __nv_bfloat16 g_hhi[(size_t)M_ * H_];
__device__ __align__(256) __nv_bfloat16 g_hlo[(size_t)M_ * H_];
__device__ __align__(256) __nv_bfloat16 g_xhi[(size_t)M_ * D_];
__device__ __align__(256) __nv_bfloat16 g_xlo[(size_t)M_ * D_];
__device__ __align__(256) __nv_bfloat16 g_wbhi[(size_t)H_ * D_];
__device__ __align__(256) __nv_bfloat16 g_wblo[(size_t)H_ * D_];
__device__ __align__(256) __nv_bfloat16 g_wchi[(size_t)D_ * H_];
__device__ __align__(256) __nv_bfloat16 g_wclo[(size_t)D_ * H_];
__device__ __align__(256) float         g_carry[B_ * NC_ * H_];
__device__ __align__(256) float         g_hprev[B_ * NC_ * H_];

// ---------------------------------------------------------------------------
// PTX helpers (baseline ISA only: cp.async / ldmatrix / mma.sync)
// ---------------------------------------------------------------------------
__device__ __forceinline__ uint32_t smem_to_u32(const void* p) {
    uint32_t a;
    asm("{ .reg .u64 t; cvta.to.shared.u64 t, %1; cvt.u32.u64 %0, t; }" : "=r"(a) : "l"(p));
    return a;
}
__device__ __forceinline__ void cp_async16(uint32_t dst, const void* src) {
    asm volatile("cp.async.cg.shared.global [%0], [%1], 16;" :: "r"(dst), "l"(src) : "memory");
}
__device__ __forceinline__ void cp_commit() {
    asm volatile("cp.async.commit_group;" ::: "memory");
}
__device__ __forceinline__ void cp_wait1() {
    asm volatile("cp.async.wait_group 1;" ::: "memory");
}
__device__ __forceinline__ void ldsm_x4(uint32_t* r, uint32_t addr) {
    asm volatile("ldmatrix.sync.aligned.m8n8.x4.shared.b16 {%0,%1,%2,%3}, [%4];"
                 : "=r"(r[0]), "=r"(r[1]), "=r"(r[2]), "=r"(r[3]) : "r"(addr));
}
__device__ __forceinline__ void mma_bf16(float* c, const uint32_t* a, const uint32_t* b) {
    asm volatile(
        "mma.sync.aligned.m16n8k16.row.col.f32.bf16.bf16.f32 "
        "{%0,%1,%2,%3}, {%4,%5,%6,%7}, {%8,%9}, {%0,%1,%2,%3};"
        : "+f"(c[0]), "+f"(c[1]), "+f"(c[2]), "+f"(c[3])
        : "r"(a[0]), "r"(a[1]), "r"(a[2]), "r"(a[3]), "r"(b[0]), "r"(b[1]));
}

// Swizzle: 64B rows, 4x 16B lanes; lane ^= (row%4) ^ ((row/4)%4)
__device__ __forceinline__ uint32_t sw_off(int row, int lane) {
    return (uint32_t)(row * 64 + ((lane ^ (row & 3) ^ ((row >> 2) & 3)) << 4));
}

__device__ __forceinline__ float dsigmoid(float x) { return 1.0f / (1.0f + expf(-x)); }

// ---------------------------------------------------------------------------
// Split fp32 -> (hi, lo) bf16
// ---------------------------------------------------------------------------
__global__ void split_f32(const float* __restrict__ src,
                          __nv_bfloat16* __restrict__ hi,
                          __nv_bfloat16* __restrict__ lo, int n4)
{
    int i = blockIdx.x * blockDim.x + threadIdx.x;
    if (i >= n4) return;
    float4 v = reinterpret_cast<const float4*>(src)[i];
    __nv_bfloat16 h0 = __float2bfloat16_rn(v.x);
    __nv_bfloat16 h1 = __float2bfloat16_rn(v.y);
    __nv_bfloat16 h2 = __float2bfloat16_rn(v.z);
    __nv_bfloat16 h3 = __float2bfloat16_rn(v.w);
    __nv_bfloat16 l0 = __float2bfloat16_rn(v.x - __bfloat162float(h0));
    __nv_bfloat16 l1 = __float2bfloat16_rn(v.y - __bfloat162float(h1));
    __nv_bfloat16 l2 = __float2bfloat16_rn(v.z - __bfloat162float(h2));
    __nv_bfloat16 l3 = __float2bfloat16_rn(v.w - __bfloat162float(h3));
    reinterpret_cast<__nv_bfloat162*>(hi)[2 * i + 0] = __halves2bfloat162(h0, h1);
    reinterpret_cast<__nv_bfloat162*>(hi)[2 * i + 1] = __halves2bfloat162(h2, h3);
    reinterpret_cast<__nv_bfloat162*>(lo)[2 * i + 0] = __halves2bfloat162(l0, l1);
    reinterpret_cast<__nv_bfloat162*>(lo)[2 * i + 1] = __halves2bfloat162(l2, l3);
}

// ---------------------------------------------------------------------------
// Split-bf16 x3 GEMM (NT) via mma.sync:
//   C[M,N] (+)= (Ahi+Alo)[M,Klen] @ ((Bhi+Blo)[N,Klen])^T (+ bias[N])
// BM=128, BN=64, BK=32; 8 warps (4m x 2n), warp tile 32x32.
// 3-stage cp.async pipeline; 24KB/stage -> 72KB smem -> 3 CTAs/SM.
// If carryOut != null (GEMM1 path): the 128 M-rows of this tile are one
// (batch, chunk) slab; epilogue also computes carry[b,chunk,col] =
// sum_i a^(127-i) * (acc_i + bias) with a = sigmoid(Araw[col]).
// ---------------------------------------------------------------------------
#define BM_ 128
#define BN_ 64
#define BK_ 32
#define NSTAGE_ 3
#define STG_ 24576
#define T_AHI 0
#define T_ALO 8192
#define T_BHI 16384
#define T_BLO 20480

__device__ __forceinline__ void load_stage(
    uint32_t st, int tid, const char* Ahi, const char* Alo,
    const char* Bhi, const char* Blo, size_t rowbytes, int bm, int bn, int k0byte)
{
#pragma unroll
    for (int i = 0; i < 2; i++) {
        int l = tid + i * 256;          // 0..511 lanes of 16B (A: 128 rows x 4)
        int r = l >> 2, c = l & 3;
        uint32_t sw = sw_off(r, c);
        size_t ga = (size_t)(bm + r) * rowbytes + k0byte + c * 16;
        cp_async16(st + T_AHI + sw, Ahi + ga);
        cp_async16(st + T_ALO + sw, Alo + ga);
    }
    {
        int r = tid >> 2, c = tid & 3;  // B: 64 rows x 4 lanes = 256
        uint32_t sw = sw_off(r, c);
        size_t gb = (size_t)(bn + r) * rowbytes + k0byte + c * 16;
        cp_async16(st + T_BHI + sw, Bhi + gb);
        cp_async16(st + T_BLO + sw, Blo + gb);
    }
}

__global__ __launch_bounds__(256, 3)
void gemm_split3(const __nv_bfloat16* __restrict__ Ahi, const __nv_bfloat16* __restrict__ Alo,
                 const __nv_bfloat16* __restrict__ Bhi, const __nv_bfloat16* __restrict__ Blo,
                 const float* __restrict__ bias, float* __restrict__ C,
                 int N, int K, int Klen, size_t zstride,
                 const float* __restrict__ Araw, float* __restrict__ carryOut)
{
    extern __shared__ char smem[];
    const uint32_t sb = smem_to_u32(smem);
    const int tid = threadIdx.x;
    const int wid = tid >> 5, lid = tid & 31;
    const int wm = wid & 3, wn = wid >> 2;        // 4(m) x 2(n) warp grid
    const int bm = blockIdx.y * BM_;
    const int bn = blockIdx.x * BN_;
    const size_t rowbytes = (size_t)K * 2;
    const int NKC = Klen / BK_;
    const size_t kofs = (size_t)blockIdx.z * Klen * 2;

    const char* pAh = (const char*)Ahi + kofs;
    const char* pAl = (const char*)Alo + kofs;
    const char* pBh = (const char*)Bhi + kofs;
    const char* pBl = (const char*)Blo + kofs;
    C += (size_t)blockIdx.z * zstride;

    float acc[2][4][4];
#pragma unroll
    for (int mt = 0; mt < 2; mt++)
#pragma unroll
        for (int nt = 0; nt < 4; nt++)
#pragma unroll
            for (int j = 0; j < 4; j++) acc[mt][nt][j] = 0.0f;

    // Prologue: stages 0..1
#pragma unroll
    for (int s = 0; s < NSTAGE_ - 1; s++) {
        if (s < NKC) load_stage(sb + s * STG_, tid, pAh, pAl, pBh, pBl, rowbytes, bm, bn, s * BK_ * 2);
        cp_commit();
    }

#pragma unroll 1
    for (int kc = 0; kc < NKC; kc++) {
        cp_wait1();
        __syncthreads();
        {
            int nx = kc + NSTAGE_ - 1;
            if (nx < NKC)
                load_stage(sb + (nx % NSTAGE_) * STG_, tid, pAh, pAl, pBh, pBl, rowbytes, bm, bn, nx * BK_ * 2);
            cp_commit();
        }
        const uint32_t st = sb + (kc % NSTAGE_) * STG_;

#pragma unroll
        for (int kst = 0; kst < 2; kst++) {
            uint32_t ah[2][4], al[2][4], bh[2][4], bl[2][4];
#pragma unroll
            for (int mt = 0; mt < 2; mt++) {
                int row = wm * 32 + mt * 16 + (lid & 15);
                int lane = kst * 2 + (lid >> 4);
                uint32_t off = sw_off(row, lane);
                ldsm_x4(ah[mt], st + T_AHI + off);
                ldsm_x4(al[mt], st + T_ALO + off);
            }
#pragma unroll
            for (int nt2 = 0; nt2 < 2; nt2++) {
                int row = wn * 32 + nt2 * 16 + (lid & 7) + ((lid >> 4) << 3);
                int lane = kst * 2 + ((lid >> 3) & 1);
                uint32_t off = sw_off(row, lane);
                ldsm_x4(bh[nt2], st + T_BHI + off);
                ldsm_x4(bl[nt2], st + T_BLO + off);
            }
#pragma unroll
            for (int mt = 0; mt < 2; mt++)
#pragma unroll
                for (int nt = 0; nt < 4; nt++) {
                    const uint32_t* bfh = &bh[nt >> 1][(nt & 1) * 2];
                    const uint32_t* bfl = &bl[nt >> 1][(nt & 1) * 2];
                    mma_bf16(acc[mt][nt], ah[mt], bfh);   // hi*hi
                    mma_bf16(acc[mt][nt], al[mt], bfh);   // lo*hi
                    mma_bf16(acc[mt][nt], ah[mt], bfl);   // hi*lo
                }
        }
        __syncthreads();
    }

    // ---------------- Epilogue: add bias (if any), store fp32 ----------------
    const int q2 = lid >> 2;                       // 0..7
    const int r0 = bm + wm * 32 + q2;
    const int cq = (lid & 3) * 2;
#pragma unroll
    for (int mt = 0; mt < 2; mt++) {
#pragma unroll
        for (int nt = 0; nt < 4; nt++) {
            int col = bn + wn * 32 + nt * 8 + cq;
            float bx = 0.0f, by = 0.0f;
            if (bias) { bx = bias[col]; by = bias[col + 1]; }
            float2 v0 = make_float2(acc[mt][nt][0] + bx, acc[mt][nt][1] + by);
            float2 v1 = make_float2(acc[mt][nt][2] + bx, acc[mt][nt][3] + by);
            *reinterpret_cast<float2*>(&C[(size_t)(r0 + mt * 16) * N + col]) = v0;
            *reinterpret_cast<float2*>(&C[(size_t)(r0 + mt * 16 + 8) * N + col]) = v1;
        }
    }

    // ------------- Fused scan-carry reduction (GEMM1 only) -------------------
    if (carryOut) {
        float* smc = (float*)smem;                 // 4 x 64 floats (reuse stage 0)
        float contrib[8];
        const int cbase = wn * 32 + cq;
#pragma unroll
        for (int nt = 0; nt < 4; nt++) {
#pragma unroll
            for (int e = 0; e < 2; e++) {
                int cl = cbase + nt * 8 + e;
                float a = dsigmoid(Araw[bn + cl]);
                float bc = bias[bn + cl];
                float a2 = a * a, a4 = a2 * a2, a8 = a4 * a4;
                float a16 = a8 * a8, a32 = a16 * a16;
                // rows q, q+8, q+16, q+24  (q = wm*32 + q2)
                float T = acc[0][nt][e] + bc;
                T = T * a8 + (acc[0][nt][2 + e] + bc);
                T = T * a8 + (acc[1][nt][e] + bc);
                T = T * a8 + (acc[1][nt][2 + e] + bc);
                // contribution = a^(103 - wm*32 - q2) * T
                float p = 1.0f;
                for (int t = 0; t < 7 - q2; t++) p *= a;
                for (int t = 0; t < 3 - wm; t++) p *= a32;
                contrib[nt * 2 + e] = T * p;
            }
        }
        // reduce over q2 (lid bits 2..4)
#pragma unroll
        for (int ofs = 4; ofs <= 16; ofs <<= 1)
#pragma unroll
            for (int j = 0; j < 8; j++)
                contrib[j] += __shfl_xor_sync(0xffffffffu, contrib[j], ofs);
        if (q2 == 0) {
#pragma unroll
            for (int nt = 0; nt < 4; nt++) {
                smc[wm * 64 + cbase + nt * 8 + 0] = contrib[nt * 2 + 0];
                smc[wm * 64 + cbase + nt * 8 + 1] = contrib[nt * 2 + 1];
            }
        }
        __syncthreads();
        if (tid < 64) {
            float s = smc[tid] + smc[64 + tid] + smc[128 + tid] + smc[192 + tid];
            int bb2 = bm >> 11;                    // batch
            int ch = (bm >> 7) & (NC_ - 1);        // chunk
            carryOut[(size_t)bb2 * (NC_ * H_) + (size_t)ch * H_ + bn + tid] = s;
        }
    }
}

// Split-K reduce: out[i] = p0[i] + p1[i] + bias[col]
__global__ void reduce_splitk(const float* __restrict__ part, const float* __restrict__ bias,
                              float* __restrict__ out, int n4, size_t zstride4, int Nmask4)
{
    int i = blockIdx.x * blockDim.x + threadIdx.x;
    if (i >= n4) return;
    float4 a = reinterpret_cast<const float4*>(part)[i];
    float4 b = reinterpret_cast<const float4*>(part)[i + zstride4];
    int col = (i & Nmask4) * 4;
    float4 v;
    v.x = a.x + b.x + bias[col + 0];
    v.y = a.y + b.y + bias[col + 1];
    v.z = a.z + b.z + bias[col + 2];
    v.w = a.w + b.w + bias[col + 3];
    reinterpret_cast<float4*>(out)[i] = v;
}

// ---------------------------------------------------------------------------
// Scan phases (carry reduction now fused into GEMM1 epilogue)
// ---------------------------------------------------------------------------
__global__ void scan_phaseB(const float* __restrict__ carry, const float* __restrict__ Araw,
                            float* __restrict__ hprev)
{
    int idx = blockIdx.x * blockDim.x + threadIdx.x;   // [B, H]
    int h = idx & (H_ - 1);
    int bb = idx >> 12;
    float a = dsigmoid(Araw[h]);
    float aC = a;
#pragma unroll
    for (int i = 0; i < 7; i++) aC *= aC;              // a^128
    float run = 0.0f;
#pragma unroll
    for (int c = 0; c < NC_; c++) {
        size_t off = ((size_t)bb * NC_ + c) * H_ + h;
        hprev[off] = run;
        run = fmaf(aC, run, carry[off]);
    }
}

__global__ void scan_phaseC(const float* __restrict__ bbuf, const float* __restrict__ Araw,
                            const float* __restrict__ hprev,
                            __nv_bfloat16* __restrict__ hhi, __nv_bfloat16* __restrict__ hlo)
{
    int idx = blockIdx.x * blockDim.x + threadIdx.x;   // [B, NC, H]
    int h = idx & (H_ - 1);
    int c = (idx >> 12) & (NC_ - 1);
    int bb = idx >> 16;
    float a = dsigmoid(Araw[h]);
    float Hp = hprev[idx];
    size_t base = ((size_t)bb * L_ + (size_t)c * CHUNK_) * H_ + h;
    float s = 0.0f, p = 1.0f;
#pragma unroll 8
    for (int i = 0; i < CHUNK_; i++) {
        size_t off = base + (size_t)i * H_;
        p *= a;                        // a^(i+1)
        s = fmaf(a, s, bbuf[off]);     // local inclusive scan
        float v = fmaf(p, Hp, s);      // + carry-in contribution
        __nv_bfloat16 hi = __float2bfloat16_rn(v);
        hhi[off] = hi;
        hlo[off] = __float2bfloat16_rn(v - __bfloat162float(hi));
    }
}

// ---------------------------------------------------------------------------
extern "C" void kernel_launch(void* const* d_in, const int* in_sizes, int n_in,
                              void* d_out, int out_size)
{
    const float* x  = (const float*)d_in[0];   // [B, L, D]
    const float* WB = (const float*)d_in[1];   // [H, D]
    const float* bB = (const float*)d_in[2];   // [H]
    const float* WC = (const float*)d_in[3];   // [D, H]
    const float* bC = (const float*)d_in[4];   // [D]
    const float* A  = (const float*)d_in[5];   // [H]
    float* out = (float*)d_out;                // [B, L, D]

    float *bbuf, *carry, *hprev;
    __nv_bfloat16 *xhi, *xlo, *wbhi, *wblo, *wchi, *wclo, *hhi, *hlo;
    cudaGetSymbolAddress((void**)&bbuf, g_b);
    cudaGetSymbolAddress((void**)&carry, g_carry);
    cudaGetSymbolAddress((void**)&hprev, g_hprev);
    cudaGetSymbolAddress((void**)&xhi, g_xhi);
    cudaGetSymbolAddress((void**)&xlo, g_xlo);
    cudaGetSymbolAddress((void**)&wbhi, g_wbhi);
    cudaGetSymbolAddress((void**)&wblo, g_wblo);
    cudaGetSymbolAddress((void**)&wchi, g_wchi);
    cudaGetSymbolAddress((void**)&wclo, g_wclo);
    cudaGetSymbolAddress((void**)&hhi, g_hhi);
    cudaGetSymbolAddress((void**)&hlo, g_hlo);

    const int SMEM_G = NSTAGE_ * STG_;     // 72 KB -> 3 CTAs/SM
    cudaFuncSetAttribute(gemm_split3, cudaFuncAttributeMaxDynamicSharedMemorySize, SMEM_G);

    // Split inputs to bf16 hi/lo
    split_f32<<<(M_ * D_ / 4 + 255) / 256, 256>>>(x, xhi, xlo, M_ * D_ / 4);
    split_f32<<<(H_ * D_ / 4 + 255) / 256, 256>>>(WB, wbhi, wblo, H_ * D_ / 4);
    split_f32<<<(D_ * H_ / 4 + 255) / 256, 256>>>(WC, wchi, wclo, D_ * H_ / 4);

    // GEMM1: b = x @ WB^T + bB   (M=8192, N=4096, K=256) + fused chunk-carry
    gemm_split3<<<dim3(H_ / BN_, M_ / BM_, 1), 256, SMEM_G>>>(
        xhi, xlo, wbhi, wblo, bB, bbuf, H_, D_, D_, 0, A, carry);

    // Scan over L
    scan_phaseB<<<(B_ * H_) / 256, 256>>>(carry, A, hprev);
    scan_phaseC<<<(B_ * NC_ * H_) / 256, 256>>>(bbuf, A, hprev, hhi, hlo);

    // GEMM2: out = h @ WC^T + bC  (M=8192, N=256, K=4096), split-K=2.
    const size_t zstride = (size_t)M_ * D_;
    gemm_split3<<<dim3(D_ / BN_, M_ / BM_, 2), 256, SMEM_G>>>(
        hhi, hlo, wchi, wclo, nullptr, bbuf, D_, H_, H_ / 2, zstride, nullptr, nullptr);
    reduce_splitk<<<(M_ * D_ / 4 + 255) / 256, 256>>>(
        bbuf, bC, out, M_ * D_ / 4, zstride / 4, (D_ / 4) - 1);
}

// round 6
// speedup vs baseline: 1.5003x; 1.5003x over previous
#include <cuda_runtime.h>
#include <cuda_bf16.h>
#include <cstdint>
#include <math.h>

// ---------------------------------------------------------------------------
// Problem constants
// ---------------------------------------------------------------------------
#define B_ 4
#define L_ 2048
#define D_ 256
#define H_ 4096
#define M_ (B_ * L_)          // 8192
#define CHUNK_ 128
#define NC_ (L_ / CHUNK_)     // 16

// ---------------------------------------------------------------------------
// Scratch (device globals; no allocation allowed)
// g_b holds b [M,H] fp32 for the scan; dead after phaseC, so GEMM2's split-K
// partials (2 x M x D fp32) reuse its space.
// ---------------------------------------------------------------------------
__device__ __align__(256) float         g_b[(size_t)M_ * H_];      // 128 MB
__device__ __align__(256) __nv_bfloat16 g_hhi[(size_t)M_ * H_];
__device__ __align__(256) __nv_bfloat16 g_hlo[(size_t)M_ * H_];
__device__ __align__(256) __nv_bfloat16 g_xhi[(size_t)M_ * D_];
__device__ __align__(256) __nv_bfloat16 g_xlo[(size_t)M_ * D_];
__device__ __align__(256) __nv_bfloat16 g_wbhi[(size_t)H_ * D_];
__device__ __align__(256) __nv_bfloat16 g_wblo[(size_t)H_ * D_];
__device__ __align__(256) __nv_bfloat16 g_wchi[(size_t)D_ * H_];
__device__ __align__(256) __nv_bfloat16 g_wclo[(size_t)D_ * H_];
__device__ __align__(256) float         g_carry[B_ * NC_ * H_];
__device__ __align__(256) float         g_hprev[B_ * NC_ * H_];

// ---------------------------------------------------------------------------
// PTX helpers (baseline ISA only: cp.async / ldmatrix / mma.sync)
// ---------------------------------------------------------------------------
__device__ __forceinline__ uint32_t smem_to_u32(const void* p) {
    uint32_t a;
    asm("{ .reg .u64 t; cvta.to.shared.u64 t, %1; cvt.u32.u64 %0, t; }" : "=r"(a) : "l"(p));
    return a;
}
__device__ __forceinline__ void cp_async16(uint32_t dst, const void* src) {
    asm volatile("cp.async.cg.shared.global [%0], [%1], 16;" :: "r"(dst), "l"(src) : "memory");
}
__device__ __forceinline__ void cp_commit() {
    asm volatile("cp.async.commit_group;" ::: "memory");
}
__device__ __forceinline__ void cp_wait1() {
    asm volatile("cp.async.wait_group 1;" ::: "memory");
}
__device__ __forceinline__ void cp_wait0() {
    asm volatile("cp.async.wait_group 0;" ::: "memory");
}
__device__ __forceinline__ void ldsm_x4(uint32_t* r, uint32_t addr) {
    asm volatile("ldmatrix.sync.aligned.m8n8.x4.shared.b16 {%0,%1,%2,%3}, [%4];"
                 : "=r"(r[0]), "=r"(r[1]), "=r"(r[2]), "=r"(r[3]) : "r"(addr));
}
__device__ __forceinline__ void mma_bf16(float* c, const uint32_t* a, const uint32_t* b) {
    asm volatile(
        "mma.sync.aligned.m16n8k16.row.col.f32.bf16.bf16.f32 "
        "{%0,%1,%2,%3}, {%4,%5,%6,%7}, {%8,%9}, {%0,%1,%2,%3};"
        : "+f"(c[0]), "+f"(c[1]), "+f"(c[2]), "+f"(c[3])
        : "r"(a[0]), "r"(a[1]), "r"(a[2]), "r"(a[3]), "r"(b[0]), "r"(b[1]));
}

// Swizzle: 64B rows, 4x 16B lanes; lane ^= (row%4) ^ ((row/4)%4)
__device__ __forceinline__ uint32_t sw_off(int row, int lane) {
    return (uint32_t)(row * 64 + ((lane ^ (row & 3) ^ ((row >> 2) & 3)) << 4));
}

__device__ __forceinline__ float dsigmoid(float x) { return 1.0f / (1.0f + expf(-x)); }

// ---------------------------------------------------------------------------
// Split fp32 -> (hi, lo) bf16
// ---------------------------------------------------------------------------
__global__ void split_f32(const float* __restrict__ src,
                          __nv_bfloat16* __restrict__ hi,
                          __nv_bfloat16* __restrict__ lo, int n4)
{
    int i = blockIdx.x * blockDim.x + threadIdx.x;
    if (i >= n4) return;
    float4 v = reinterpret_cast<const float4*>(src)[i];
    __nv_bfloat16 h0 = __float2bfloat16_rn(v.x);
    __nv_bfloat16 h1 = __float2bfloat16_rn(v.y);
    __nv_bfloat16 h2 = __float2bfloat16_rn(v.z);
    __nv_bfloat16 h3 = __float2bfloat16_rn(v.w);
    __nv_bfloat16 l0 = __float2bfloat16_rn(v.x - __bfloat162float(h0));
    __nv_bfloat16 l1 = __float2bfloat16_rn(v.y - __bfloat162float(h1));
    __nv_bfloat16 l2 = __float2bfloat16_rn(v.z - __bfloat162float(h2));
    __nv_bfloat16 l3 = __float2bfloat16_rn(v.w - __bfloat162float(h3));
    reinterpret_cast<__nv_bfloat162*>(hi)[2 * i + 0] = __halves2bfloat162(h0, h1);
    reinterpret_cast<__nv_bfloat162*>(hi)[2 * i + 1] = __halves2bfloat162(h2, h3);
    reinterpret_cast<__nv_bfloat162*>(lo)[2 * i + 0] = __halves2bfloat162(l0, l1);
    reinterpret_cast<__nv_bfloat162*>(lo)[2 * i + 1] = __halves2bfloat162(l2, l3);
}

// ---------------------------------------------------------------------------
// Split-bf16 x3 GEMM (NT) via mma.sync:
//   C[M,N] (+)= (Ahi+Alo)[M,Klen] @ ((Bhi+Blo)[N,Klen])^T (+ bias[N])
// BM=128, BN=128, BK=32; 8 warps (4m x 2n), warp tile 32x64.
// 3-stage cp.async pipeline; 32KB/stage -> 96KB smem -> 2 CTAs/SM.
// One __syncthreads per mainloop iteration (top sync of iter kc+1 orders the
// WAR on the stage reused at kc+1).
// If carryOut != null (GEMM1): the tile's 128 M-rows are one (batch, chunk)
// slab; epilogue also computes carry[b,chunk,col] = sum_i a^(127-i)*(b_i)
// with a = sigmoid(Araw[col]), b_i = acc_i + bias.
// ---------------------------------------------------------------------------
#define BM_ 128
#define BN_ 128
#define BK_ 32
#define NSTAGE_ 3
#define STG_ 32768
#define T_AHI 0
#define T_ALO 8192
#define T_BHI 16384
#define T_BLO 24576

__device__ __forceinline__ void load_stage(
    uint32_t st, int tid, const char* Ahi, const char* Alo,
    const char* Bhi, const char* Blo, size_t rowbytes, int bm, int bn, int k0byte)
{
#pragma unroll
    for (int i = 0; i < 2; i++) {
        int l = tid + i * 256;          // 0..511 lanes of 16B
        int r = l >> 2, c = l & 3;
        uint32_t sw = sw_off(r, c);
        size_t ga = (size_t)(bm + r) * rowbytes + k0byte + c * 16;
        size_t gb = (size_t)(bn + r) * rowbytes + k0byte + c * 16;
        cp_async16(st + T_AHI + sw, Ahi + ga);
        cp_async16(st + T_ALO + sw, Alo + ga);
        cp_async16(st + T_BHI + sw, Bhi + gb);
        cp_async16(st + T_BLO + sw, Blo + gb);
    }
}

__global__ __launch_bounds__(256, 2)
void gemm_split3(const __nv_bfloat16* __restrict__ Ahi, const __nv_bfloat16* __restrict__ Alo,
                 const __nv_bfloat16* __restrict__ Bhi, const __nv_bfloat16* __restrict__ Blo,
                 const float* __restrict__ bias, float* __restrict__ C,
                 int N, int K, int Klen, size_t zstride,
                 const float* __restrict__ Araw, float* __restrict__ carryOut)
{
    extern __shared__ char smem[];
    const uint32_t sb = smem_to_u32(smem);
    const int tid = threadIdx.x;
    const int wid = tid >> 5, lid = tid & 31;
    const int wm = wid & 3, wn = wid >> 2;        // 4(m) x 2(n) warp grid
    const int bm = blockIdx.y * BM_;
    const int bn = blockIdx.x * BN_;
    const size_t rowbytes = (size_t)K * 2;
    const int NKC = Klen / BK_;
    const size_t kofs = (size_t)blockIdx.z * Klen * 2;

    const char* pAh = (const char*)Ahi + kofs;
    const char* pAl = (const char*)Alo + kofs;
    const char* pBh = (const char*)Bhi + kofs;
    const char* pBl = (const char*)Blo + kofs;
    C += (size_t)blockIdx.z * zstride;

    float acc[2][8][4];
#pragma unroll
    for (int mt = 0; mt < 2; mt++)
#pragma unroll
        for (int nt = 0; nt < 8; nt++)
#pragma unroll
            for (int j = 0; j < 4; j++) acc[mt][nt][j] = 0.0f;

    // Prologue: stages 0..1
#pragma unroll
    for (int s = 0; s < NSTAGE_ - 1; s++) {
        if (s < NKC) load_stage(sb + s * STG_, tid, pAh, pAl, pBh, pBl, rowbytes, bm, bn, s * BK_ * 2);
        cp_commit();
    }

#pragma unroll 1
    for (int kc = 0; kc < NKC; kc++) {
        cp_wait1();
        __syncthreads();
        {
            int nx = kc + NSTAGE_ - 1;
            if (nx < NKC)
                load_stage(sb + (nx % NSTAGE_) * STG_, tid, pAh, pAl, pBh, pBl, rowbytes, bm, bn, nx * BK_ * 2);
            cp_commit();
        }
        const uint32_t st = sb + (kc % NSTAGE_) * STG_;

#pragma unroll
        for (int kst = 0; kst < 2; kst++) {
            uint32_t ah[2][4], al[2][4], bh[4][4], bl[4][4];
#pragma unroll
            for (int mt = 0; mt < 2; mt++) {
                int row = wm * 32 + mt * 16 + (lid & 15);
                int lane = kst * 2 + (lid >> 4);
                uint32_t off = sw_off(row, lane);
                ldsm_x4(ah[mt], st + T_AHI + off);
                ldsm_x4(al[mt], st + T_ALO + off);
            }
#pragma unroll
            for (int nt2 = 0; nt2 < 4; nt2++) {
                int row = wn * 64 + nt2 * 16 + (lid & 7) + ((lid >> 4) << 3);
                int lane = kst * 2 + ((lid >> 3) & 1);
                uint32_t off = sw_off(row, lane);
                ldsm_x4(bh[nt2], st + T_BHI + off);
                ldsm_x4(bl[nt2], st + T_BLO + off);
            }
#pragma unroll
            for (int mt = 0; mt < 2; mt++)
#pragma unroll
                for (int nt = 0; nt < 8; nt++) {
                    const uint32_t* bfh = &bh[nt >> 1][(nt & 1) * 2];
                    const uint32_t* bfl = &bl[nt >> 1][(nt & 1) * 2];
                    mma_bf16(acc[mt][nt], ah[mt], bfh);   // hi*hi
                    mma_bf16(acc[mt][nt], al[mt], bfh);   // lo*hi
                    mma_bf16(acc[mt][nt], ah[mt], bfl);   // hi*lo
                }
        }
        // no bottom sync: top sync of next iteration orders stage reuse
    }

    // ---------------- Epilogue: add bias (if any), store fp32 ----------------
    const int q2 = lid >> 2;                       // 0..7
    const int r0 = bm + wm * 32 + q2;
    const int cq = (lid & 3) * 2;
#pragma unroll
    for (int mt = 0; mt < 2; mt++) {
#pragma unroll
        for (int nt = 0; nt < 8; nt++) {
            int col = bn + wn * 64 + nt * 8 + cq;
            float bx = 0.0f, by = 0.0f;
            if (bias) { bx = bias[col]; by = bias[col + 1]; }
            float2 v0 = make_float2(acc[mt][nt][0] + bx, acc[mt][nt][1] + by);
            float2 v1 = make_float2(acc[mt][nt][2] + bx, acc[mt][nt][3] + by);
            *reinterpret_cast<float2*>(&C[(size_t)(r0 + mt * 16) * N + col]) = v0;
            *reinterpret_cast<float2*>(&C[(size_t)(r0 + mt * 16 + 8) * N + col]) = v1;
        }
    }

    // ------------- Fused scan-carry reduction (GEMM1 only) -------------------
    if (carryOut) {
        cp_wait0();
        __syncthreads();                           // all smem traffic done
        float* smc = (float*)smem;                 // 4 x 128 floats
        float contrib[16];
        const int cbase = wn * 64 + cq;
#pragma unroll
        for (int nt = 0; nt < 8; nt++) {
#pragma unroll
            for (int e = 0; e < 2; e++) {
                int cl = cbase + nt * 8 + e;
                float a = dsigmoid(Araw[bn + cl]);
                float bc = bias[bn + cl];
                float a8 = a * a; a8 = a8 * a8; a8 = a8 * a8;          // a^8
                float a32 = a8 * a8; a32 = a32 * a32;                   // a^32
                // rows q, q+8, q+16, q+24  (q = wm*32 + q2)
                float T = acc[0][nt][e] + bc;
                T = T * a8 + (acc[0][nt][2 + e] + bc);
                T = T * a8 + (acc[1][nt][e] + bc);
                T = T * a8 + (acc[1][nt][2 + e] + bc);
                // contribution = a^(103 - wm*32 - q2) * T
                float p = 1.0f;
                for (int t = 0; t < 7 - q2; t++) p *= a;
                for (int t = 0; t < 3 - wm; t++) p *= a32;
                contrib[nt * 2 + e] = T * p;
            }
        }
        // reduce over q2 (lid bits 2..4)
#pragma unroll
        for (int ofs = 4; ofs <= 16; ofs <<= 1)
#pragma unroll
            for (int j = 0; j < 16; j++)
                contrib[j] += __shfl_xor_sync(0xffffffffu, contrib[j], ofs);
        if (q2 == 0) {
#pragma unroll
            for (int nt = 0; nt < 8; nt++) {
                smc[wm * 128 + cbase + nt * 8 + 0] = contrib[nt * 2 + 0];
                smc[wm * 128 + cbase + nt * 8 + 1] = contrib[nt * 2 + 1];
            }
        }
        __syncthreads();
        if (tid < 128) {
            float s = smc[tid] + smc[128 + tid] + smc[256 + tid] + smc[384 + tid];
            int bb2 = bm >> 11;                    // batch
            int ch = (bm >> 7) & (NC_ - 1);        // chunk
            carryOut[(size_t)bb2 * (NC_ * H_) + (size_t)ch * H_ + bn + tid] = s;
        }
    }
}

// Split-K reduce: out[i] = p0[i] + p1[i] + bias[col]
__global__ void reduce_splitk(const float* __restrict__ part, const float* __restrict__ bias,
                              float* __restrict__ out, int n4, size_t zstride4, int Nmask4)
{
    int i = blockIdx.x * blockDim.x + threadIdx.x;
    if (i >= n4) return;
    float4 a = reinterpret_cast<const float4*>(part)[i];
    float4 b = reinterpret_cast<const float4*>(part)[i + zstride4];
    int col = (i & Nmask4) * 4;
    float4 v;
    v.x = a.x + b.x + bias[col + 0];
    v.y = a.y + b.y + bias[col + 1];
    v.z = a.z + b.z + bias[col + 2];
    v.w = a.w + b.w + bias[col + 3];
    reinterpret_cast<float4*>(out)[i] = v;
}

// ---------------------------------------------------------------------------
// Scan phases (carry reduction fused into GEMM1 epilogue)
// ---------------------------------------------------------------------------
__global__ void scan_phaseB(const float* __restrict__ carry, const float* __restrict__ Araw,
                            float* __restrict__ hprev)
{
    int idx = blockIdx.x * blockDim.x + threadIdx.x;   // [B, H]
    int h = idx & (H_ - 1);
    int bb = idx >> 12;
    float a = dsigmoid(Araw[h]);
    float aC = a;
#pragma unroll
    for (int i = 0; i < 7; i++) aC *= aC;              // a^128
    float run = 0.0f;
#pragma unroll
    for (int c = 0; c < NC_; c++) {
        size_t off = ((size_t)bb * NC_ + c) * H_ + h;
        hprev[off] = run;
        run = fmaf(aC, run, carry[off]);
    }
}

__global__ void scan_phaseC(const float* __restrict__ bbuf, const float* __restrict__ Araw,
                            const float* __restrict__ hprev,
                            __nv_bfloat16* __restrict__ hhi, __nv_bfloat16* __restrict__ hlo)
{
    int idx = blockIdx.x * blockDim.x + threadIdx.x;   // [B, NC, H]
    int h = idx & (H_ - 1);
    int c = (idx >> 12) & (NC_ - 1);
    int bb = idx >> 16;
    float a = dsigmoid(Araw[h]);
    float Hp = hprev[idx];
    size_t base = ((size_t)bb * L_ + (size_t)c * CHUNK_) * H_ + h;
    float s = 0.0f, p = 1.0f;
#pragma unroll 8
    for (int i = 0; i < CHUNK_; i++) {
        size_t off = base + (size_t)i * H_;
        p *= a;                        // a^(i+1)
        s = fmaf(a, s, bbuf[off]);     // local inclusive scan
        float v = fmaf(p, Hp, s);      // + carry-in contribution
        __nv_bfloat16 hi = __float2bfloat16_rn(v);
        hhi[off] = hi;
        hlo[off] = __float2bfloat16_rn(v - __bfloat162float(hi));
    }
}

// ---------------------------------------------------------------------------
extern "C" void kernel_launch(void* const* d_in, const int* in_sizes, int n_in,
                              void* d_out, int out_size)
{
    const float* x  = (const float*)d_in[0];   // [B, L, D]
    const float* WB = (const float*)d_in[1];   // [H, D]
    const float* bB = (const float*)d_in[2];   // [H]
    const float* WC = (const float*)d_in[3];   // [D, H]
    const float* bC = (const float*)d_in[4];   // [D]
    const float* A  = (const float*)d_in[5];   // [H]
    float* out = (float*)d_out;                // [B, L, D]

    float *bbuf, *carry, *hprev;
    __nv_bfloat16 *xhi, *xlo, *wbhi, *wblo, *wchi, *wclo, *hhi, *hlo;
    cudaGetSymbolAddress((void**)&bbuf, g_b);
    cudaGetSymbolAddress((void**)&carry, g_carry);
    cudaGetSymbolAddress((void**)&hprev, g_hprev);
    cudaGetSymbolAddress((void**)&xhi, g_xhi);
    cudaGetSymbolAddress((void**)&xlo, g_xlo);
    cudaGetSymbolAddress((void**)&wbhi, g_wbhi);
    cudaGetSymbolAddress((void**)&wblo, g_wblo);
    cudaGetSymbolAddress((void**)&wchi, g_wchi);
    cudaGetSymbolAddress((void**)&wclo, g_wclo);
    cudaGetSymbolAddress((void**)&hhi, g_hhi);
    cudaGetSymbolAddress((void**)&hlo, g_hlo);

    const int SMEM_G = NSTAGE_ * STG_;     // 96 KB -> 2 CTAs/SM
    cudaFuncSetAttribute(gemm_split3, cudaFuncAttributeMaxDynamicSharedMemorySize, SMEM_G);

    // Split inputs to bf16 hi/lo
    split_f32<<<(M_ * D_ / 4 + 255) / 256, 256>>>(x, xhi, xlo, M_ * D_ / 4);
    split_f32<<<(H_ * D_ / 4 + 255) / 256, 256>>>(WB, wbhi, wblo, H_ * D_ / 4);
    split_f32<<<(D_ * H_ / 4 + 255) / 256, 256>>>(WC, wchi, wclo, D_ * H_ / 4);

    // GEMM1: b = x @ WB^T + bB   (M=8192, N=4096, K=256) + fused chunk-carry
    gemm_split3<<<dim3(H_ / BN_, M_ / BM_, 1), 256, SMEM_G>>>(
        xhi, xlo, wbhi, wblo, bB, bbuf, H_, D_, D_, 0, A, carry);

    // Scan over L
    scan_phaseB<<<(B_ * H_) / 256, 256>>>(carry, A, hprev);
    scan_phaseC<<<(B_ * NC_ * H_) / 256, 256>>>(bbuf, A, hprev, hhi, hlo);

    // GEMM2: out = h @ WC^T + bC  (M=8192, N=256, K=4096), split-K=2.
    const size_t zstride = (size_t)M_ * D_;
    gemm_split3<<<dim3(D_ / BN_, M_ / BM_, 2), 256, SMEM_G>>>(
        hhi, hlo, wchi, wclo, nullptr, bbuf, D_, H_, H_ / 2, zstride, nullptr, nullptr);
    reduce_splitk<<<(M_ * D_ / 4 + 255) / 256, 256>>>(
        bbuf, bC, out, M_ * D_ / 4, zstride / 4, (D_ / 4) - 1);
}

// round 7
// speedup vs baseline: 1.5739x; 1.0490x over previous
#include <cuda_runtime.h>
#include <cuda_bf16.h>
#include <cstdint>
#include <math.h>

// ---------------------------------------------------------------------------
// Problem constants
// ---------------------------------------------------------------------------
#define B_ 4
#define L_ 2048
#define D_ 256
#define H_ 4096
#define M_ (B_ * L_)          // 8192
#define CHUNK_ 128
#define NC_ (L_ / CHUNK_)     // 16

// ---------------------------------------------------------------------------
// Scratch (device globals; no allocation allowed)
// g_b holds b [M,H] fp32 for the scan; dead after phaseC, so GEMM2's split-K
// partials (2 x M x D fp32) reuse its space.
// ---------------------------------------------------------------------------
__device__ __align__(256) float         g_b[(size_t)M_ * H_];      // 128 MB
__device__ __align__(256) __nv_bfloat16 g_hhi[(size_t)M_ * H_];
__device__ __align__(256) __nv_bfloat16 g_hlo[(size_t)M_ * H_];
__device__ __align__(256) __nv_bfloat16 g_xhi[(size_t)M_ * D_];
__device__ __align__(256) __nv_bfloat16 g_xlo[(size_t)M_ * D_];
__device__ __align__(256) __nv_bfloat16 g_wbhi[(size_t)H_ * D_];
__device__ __align__(256) __nv_bfloat16 g_wblo[(size_t)H_ * D_];
__device__ __align__(256) __nv_bfloat16 g_wchi[(size_t)D_ * H_];
__device__ __align__(256) __nv_bfloat16 g_wclo[(size_t)D_ * H_];
__device__ __align__(256) float         g_carry[B_ * NC_ * H_];
__device__ __align__(256) float         g_hprev[B_ * NC_ * H_];

// ---------------------------------------------------------------------------
// PTX helpers (baseline ISA only: cp.async / ldmatrix / mma.sync)
// ---------------------------------------------------------------------------
__device__ __forceinline__ uint32_t smem_to_u32(const void* p) {
    uint32_t a;
    asm("{ .reg .u64 t; cvta.to.shared.u64 t, %1; cvt.u32.u64 %0, t; }" : "=r"(a) : "l"(p));
    return a;
}
__device__ __forceinline__ void cp_async16(uint32_t dst, const void* src) {
    asm volatile("cp.async.cg.shared.global [%0], [%1], 16;" :: "r"(dst), "l"(src) : "memory");
}
__device__ __forceinline__ void cp_commit() {
    asm volatile("cp.async.commit_group;" ::: "memory");
}
__device__ __forceinline__ void cp_wait1() {
    asm volatile("cp.async.wait_group 1;" ::: "memory");
}
__device__ __forceinline__ void ldsm_x4(uint32_t* r, uint32_t addr) {
    asm volatile("ldmatrix.sync.aligned.m8n8.x4.shared.b16 {%0,%1,%2,%3}, [%4];"
                 : "=r"(r[0]), "=r"(r[1]), "=r"(r[2]), "=r"(r[3]) : "r"(addr));
}
__device__ __forceinline__ void mma_bf16(float* c, const uint32_t* a, const uint32_t* b) {
    asm volatile(
        "mma.sync.aligned.m16n8k16.row.col.f32.bf16.bf16.f32 "
        "{%0,%1,%2,%3}, {%4,%5,%6,%7}, {%8,%9}, {%0,%1,%2,%3};"
        : "+f"(c[0]), "+f"(c[1]), "+f"(c[2]), "+f"(c[3])
        : "r"(a[0]), "r"(a[1]), "r"(a[2]), "r"(a[3]), "r"(b[0]), "r"(b[1]));
}

// Swizzle: 64B rows, 4x 16B lanes; lane ^= (row%4) ^ ((row/4)%4)
__device__ __forceinline__ uint32_t sw_off(int row, int lane) {
    return (uint32_t)(row * 64 + ((lane ^ (row & 3) ^ ((row >> 2) & 3)) << 4));
}

__device__ __forceinline__ float dsigmoid(float x) { return 1.0f / (1.0f + expf(-x)); }

// ---------------------------------------------------------------------------
// Split fp32 -> (hi, lo) bf16
// ---------------------------------------------------------------------------
__global__ void split_f32(const float* __restrict__ src,
                          __nv_bfloat16* __restrict__ hi,
                          __nv_bfloat16* __restrict__ lo, int n4)
{
    int i = blockIdx.x * blockDim.x + threadIdx.x;
    if (i >= n4) return;
    float4 v = reinterpret_cast<const float4*>(src)[i];
    __nv_bfloat16 h0 = __float2bfloat16_rn(v.x);
    __nv_bfloat16 h1 = __float2bfloat16_rn(v.y);
    __nv_bfloat16 h2 = __float2bfloat16_rn(v.z);
    __nv_bfloat16 h3 = __float2bfloat16_rn(v.w);
    __nv_bfloat16 l0 = __float2bfloat16_rn(v.x - __bfloat162float(h0));
    __nv_bfloat16 l1 = __float2bfloat16_rn(v.y - __bfloat162float(h1));
    __nv_bfloat16 l2 = __float2bfloat16_rn(v.z - __bfloat162float(h2));
    __nv_bfloat16 l3 = __float2bfloat16_rn(v.w - __bfloat162float(h3));
    reinterpret_cast<__nv_bfloat162*>(hi)[2 * i + 0] = __halves2bfloat162(h0, h1);
    reinterpret_cast<__nv_bfloat162*>(hi)[2 * i + 1] = __halves2bfloat162(h2, h3);
    reinterpret_cast<__nv_bfloat162*>(lo)[2 * i + 0] = __halves2bfloat162(l0, l1);
    reinterpret_cast<__nv_bfloat162*>(lo)[2 * i + 1] = __halves2bfloat162(l2, l3);
}

// ---------------------------------------------------------------------------
// Split-bf16 x3 GEMM (NT) via mma.sync:
//   C[M,N] (+)= (Ahi+Alo)[M,Klen] @ ((Bhi+Blo)[N,Klen])^T (+ bias[N])
// BM=128, BN=128, BK=32; 8 warps (4m x 2n), warp tile 32x64.
// 3-stage cp.async pipeline; 32KB/stage -> 96KB smem -> 2 CTAs/SM.
// MMA issue order is STREAM-OUTER: all 16 hi*hi, then 16 lo*hi, then 16 hi*lo
// -> RAW distance on any accumulator block is 16 HMMAs instead of 1.
// Per-accumulator order remains hh, lh, hl (bitwise identical results).
// ---------------------------------------------------------------------------
#define BM_ 128
#define BN_ 128
#define BK_ 32
#define NSTAGE_ 3
#define STG_ 32768
#define T_AHI 0
#define T_ALO 8192
#define T_BHI 16384
#define T_BLO 24576

__device__ __forceinline__ void load_stage(
    uint32_t st, int tid, const char* Ahi, const char* Alo,
    const char* Bhi, const char* Blo, size_t rowbytes, int bm, int bn, int k0byte)
{
#pragma unroll
    for (int i = 0; i < 2; i++) {
        int l = tid + i * 256;          // 0..511 lanes of 16B
        int r = l >> 2, c = l & 3;
        uint32_t sw = sw_off(r, c);
        size_t ga = (size_t)(bm + r) * rowbytes + k0byte + c * 16;
        size_t gb = (size_t)(bn + r) * rowbytes + k0byte + c * 16;
        cp_async16(st + T_AHI + sw, Ahi + ga);
        cp_async16(st + T_ALO + sw, Alo + ga);
        cp_async16(st + T_BHI + sw, Bhi + gb);
        cp_async16(st + T_BLO + sw, Blo + gb);
    }
}

__global__ __launch_bounds__(256, 2)
void gemm_split3(const __nv_bfloat16* __restrict__ Ahi, const __nv_bfloat16* __restrict__ Alo,
                 const __nv_bfloat16* __restrict__ Bhi, const __nv_bfloat16* __restrict__ Blo,
                 const float* __restrict__ bias, float* __restrict__ C,
                 int N, int K, int Klen, size_t zstride)
{
    extern __shared__ char smem[];
    const uint32_t sb = smem_to_u32(smem);
    const int tid = threadIdx.x;
    const int wid = tid >> 5, lid = tid & 31;
    const int wm = wid & 3, wn = wid >> 2;        // 4(m) x 2(n) warp grid
    const int bm = blockIdx.y * BM_;
    const int bn = blockIdx.x * BN_;
    const size_t rowbytes = (size_t)K * 2;
    const int NKC = Klen / BK_;
    const size_t kofs = (size_t)blockIdx.z * Klen * 2;

    const char* pAh = (const char*)Ahi + kofs;
    const char* pAl = (const char*)Alo + kofs;
    const char* pBh = (const char*)Bhi + kofs;
    const char* pBl = (const char*)Blo + kofs;
    C += (size_t)blockIdx.z * zstride;

    float acc[2][8][4];
#pragma unroll
    for (int mt = 0; mt < 2; mt++)
#pragma unroll
        for (int nt = 0; nt < 8; nt++)
#pragma unroll
            for (int j = 0; j < 4; j++) acc[mt][nt][j] = 0.0f;

    // Prologue: stages 0..1
#pragma unroll
    for (int s = 0; s < NSTAGE_ - 1; s++) {
        if (s < NKC) load_stage(sb + s * STG_, tid, pAh, pAl, pBh, pBl, rowbytes, bm, bn, s * BK_ * 2);
        cp_commit();
    }

#pragma unroll 1
    for (int kc = 0; kc < NKC; kc++) {
        cp_wait1();
        __syncthreads();
        {
            int nx = kc + NSTAGE_ - 1;
            if (nx < NKC)
                load_stage(sb + (nx % NSTAGE_) * STG_, tid, pAh, pAl, pBh, pBl, rowbytes, bm, bn, nx * BK_ * 2);
            cp_commit();
        }
        const uint32_t st = sb + (kc % NSTAGE_) * STG_;

#pragma unroll
        for (int kst = 0; kst < 2; kst++) {
            uint32_t ah[2][4], al[2][4], bh[4][4], bl[4][4];
#pragma unroll
            for (int mt = 0; mt < 2; mt++) {
                int row = wm * 32 + mt * 16 + (lid & 15);
                int lane = kst * 2 + (lid >> 4);
                uint32_t off = sw_off(row, lane);
                ldsm_x4(ah[mt], st + T_AHI + off);
                ldsm_x4(al[mt], st + T_ALO + off);
            }
#pragma unroll
            for (int nt2 = 0; nt2 < 4; nt2++) {
                int row = wn * 64 + nt2 * 16 + (lid & 7) + ((lid >> 4) << 3);
                int lane = kst * 2 + ((lid >> 3) & 1);
                uint32_t off = sw_off(row, lane);
                ldsm_x4(bh[nt2], st + T_BHI + off);
                ldsm_x4(bl[nt2], st + T_BLO + off);
            }
            // Stream-outer issue order: hh x16, lh x16, hl x16
#pragma unroll
            for (int mt = 0; mt < 2; mt++)
#pragma unroll
                for (int nt = 0; nt < 8; nt++)
                    mma_bf16(acc[mt][nt], ah[mt], &bh[nt >> 1][(nt & 1) * 2]);
#pragma unroll
            for (int mt = 0; mt < 2; mt++)
#pragma unroll
                for (int nt = 0; nt < 8; nt++)
                    mma_bf16(acc[mt][nt], al[mt], &bh[nt >> 1][(nt & 1) * 2]);
#pragma unroll
            for (int mt = 0; mt < 2; mt++)
#pragma unroll
                for (int nt = 0; nt < 8; nt++)
                    mma_bf16(acc[mt][nt], ah[mt], &bl[nt >> 1][(nt & 1) * 2]);
        }
        __syncthreads();
    }

    // Epilogue: add bias (if any), store fp32
    const int r0 = bm + wm * 32 + (lid >> 2);
    const int cq = (lid & 3) * 2;
#pragma unroll
    for (int mt = 0; mt < 2; mt++) {
#pragma unroll
        for (int nt = 0; nt < 8; nt++) {
            int col = bn + wn * 64 + nt * 8 + cq;
            float bx = 0.0f, by = 0.0f;
            if (bias) { bx = bias[col]; by = bias[col + 1]; }
            float2 v0 = make_float2(acc[mt][nt][0] + bx, acc[mt][nt][1] + by);
            float2 v1 = make_float2(acc[mt][nt][2] + bx, acc[mt][nt][3] + by);
            *reinterpret_cast<float2*>(&C[(size_t)(r0 + mt * 16) * N + col]) = v0;
            *reinterpret_cast<float2*>(&C[(size_t)(r0 + mt * 16 + 8) * N + col]) = v1;
        }
    }
}

// Split-K reduce: out[i] = p0[i] + p1[i] + bias[col]
__global__ void reduce_splitk(const float* __restrict__ part, const float* __restrict__ bias,
                              float* __restrict__ out, int n4, size_t zstride4, int Nmask4)
{
    int i = blockIdx.x * blockDim.x + threadIdx.x;
    if (i >= n4) return;
    float4 a = reinterpret_cast<const float4*>(part)[i];
    float4 b = reinterpret_cast<const float4*>(part)[i + zstride4];
    int col = (i & Nmask4) * 4;
    float4 v;
    v.x = a.x + b.x + bias[col + 0];
    v.y = a.y + b.y + bias[col + 1];
    v.z = a.z + b.z + bias[col + 2];
    v.w = a.w + b.w + bias[col + 3];
    reinterpret_cast<float4*>(out)[i] = v;
}

// ---------------------------------------------------------------------------
// Scan:  h_t = a*h_{t-1} + b_t, a = sigmoid(A[h]); chunked over L
// ---------------------------------------------------------------------------
__global__ void scan_reduceA(const float* __restrict__ bbuf, const float* __restrict__ Araw,
                             float* __restrict__ carry)
{
    int idx = blockIdx.x * blockDim.x + threadIdx.x;   // [B, NC, H]
    int h = idx & (H_ - 1);
    int c = (idx >> 12) & (NC_ - 1);
    int bb = idx >> 16;
    float a = dsigmoid(Araw[h]);
    size_t base = ((size_t)bb * L_ + (size_t)c * CHUNK_) * H_ + h;
    float s = 0.0f;
#pragma unroll 8
    for (int i = 0; i < CHUNK_; i++) s = fmaf(a, s, bbuf[base + (size_t)i * H_]);
    carry[idx] = s;
}

__global__ void scan_phaseB(const float* __restrict__ carry, const float* __restrict__ Araw,
                            float* __restrict__ hprev)
{
    int idx = blockIdx.x * blockDim.x + threadIdx.x;   // [B, H]
    int h = idx & (H_ - 1);
    int bb = idx >> 12;
    float a = dsigmoid(Araw[h]);
    float aC = a;
#pragma unroll
    for (int i = 0; i < 7; i++) aC *= aC;              // a^128
    float run = 0.0f;
#pragma unroll
    for (int c = 0; c < NC_; c++) {
        size_t off = ((size_t)bb * NC_ + c) * H_ + h;
        hprev[off] = run;
        run = fmaf(aC, run, carry[off]);
    }
}

__global__ void scan_phaseC(const float* __restrict__ bbuf, const float* __restrict__ Araw,
                            const float* __restrict__ hprev,
                            __nv_bfloat16* __restrict__ hhi, __nv_bfloat16* __restrict__ hlo)
{
    int idx = blockIdx.x * blockDim.x + threadIdx.x;   // [B, NC, H]
    int h = idx & (H_ - 1);
    int c = (idx >> 12) & (NC_ - 1);
    int bb = idx >> 16;
    float a = dsigmoid(Araw[h]);
    float Hp = hprev[idx];
    size_t base = ((size_t)bb * L_ + (size_t)c * CHUNK_) * H_ + h;
    float s = 0.0f, p = 1.0f;
#pragma unroll 8
    for (int i = 0; i < CHUNK_; i++) {
        size_t off = base + (size_t)i * H_;
        p *= a;                        // a^(i+1)
        s = fmaf(a, s, bbuf[off]);     // local inclusive scan
        float v = fmaf(p, Hp, s);      // + carry-in contribution
        __nv_bfloat16 hi = __float2bfloat16_rn(v);
        hhi[off] = hi;
        hlo[off] = __float2bfloat16_rn(v - __bfloat162float(hi));
    }
}

// ---------------------------------------------------------------------------
extern "C" void kernel_launch(void* const* d_in, const int* in_sizes, int n_in,
                              void* d_out, int out_size)
{
    const float* x  = (const float*)d_in[0];   // [B, L, D]
    const float* WB = (const float*)d_in[1];   // [H, D]
    const float* bB = (const float*)d_in[2];   // [H]
    const float* WC = (const float*)d_in[3];   // [D, H]
    const float* bC = (const float*)d_in[4];   // [D]
    const float* A  = (const float*)d_in[5];   // [H]
    float* out = (float*)d_out;                // [B, L, D]

    float *bbuf, *carry, *hprev;
    __nv_bfloat16 *xhi, *xlo, *wbhi, *wblo, *wchi, *wclo, *hhi, *hlo;
    cudaGetSymbolAddress((void**)&bbuf, g_b);
    cudaGetSymbolAddress((void**)&carry, g_carry);
    cudaGetSymbolAddress((void**)&hprev, g_hprev);
    cudaGetSymbolAddress((void**)&xhi, g_xhi);
    cudaGetSymbolAddress((void**)&xlo, g_xlo);
    cudaGetSymbolAddress((void**)&wbhi, g_wbhi);
    cudaGetSymbolAddress((void**)&wblo, g_wblo);
    cudaGetSymbolAddress((void**)&wchi, g_wchi);
    cudaGetSymbolAddress((void**)&wclo, g_wclo);
    cudaGetSymbolAddress((void**)&hhi, g_hhi);
    cudaGetSymbolAddress((void**)&hlo, g_hlo);

    const int SMEM_G = NSTAGE_ * STG_;     // 96 KB -> 2 CTAs/SM
    cudaFuncSetAttribute(gemm_split3, cudaFuncAttributeMaxDynamicSharedMemorySize, SMEM_G);

    // Split inputs to bf16 hi/lo
    split_f32<<<(M_ * D_ / 4 + 255) / 256, 256>>>(x, xhi, xlo, M_ * D_ / 4);
    split_f32<<<(H_ * D_ / 4 + 255) / 256, 256>>>(WB, wbhi, wblo, H_ * D_ / 4);
    split_f32<<<(D_ * H_ / 4 + 255) / 256, 256>>>(WC, wchi, wclo, D_ * H_ / 4);

    // GEMM1: b = x @ WB^T + bB   (M=8192, N=4096, K=256)
    gemm_split3<<<dim3(H_ / BN_, M_ / BM_, 1), 256, SMEM_G>>>(
        xhi, xlo, wbhi, wblo, bB, bbuf, H_, D_, D_, 0);

    // Scan over L
    scan_reduceA<<<(B_ * NC_ * H_) / 256, 256>>>(bbuf, A, carry);
    scan_phaseB<<<(B_ * H_) / 256, 256>>>(carry, A, hprev);
    scan_phaseC<<<(B_ * NC_ * H_) / 256, 256>>>(bbuf, A, hprev, hhi, hlo);

    // GEMM2: out = h @ WC^T + bC  (M=8192, N=256, K=4096), split-K=2.
    const size_t zstride = (size_t)M_ * D_;
    gemm_split3<<<dim3(D_ / BN_, M_ / BM_, 2), 256, SMEM_G>>>(
        hhi, hlo, wchi, wclo, nullptr, bbuf, D_, H_, H_ / 2, zstride);
    reduce_splitk<<<(M_ * D_ / 4 + 255) / 256, 256>>>(
        bbuf, bC, out, M_ * D_ / 4, zstride / 4, (D_ / 4) - 1);
}

// round 8
// speedup vs baseline: 2.0646x; 1.3118x over previous
#include <cuda_runtime.h>
#include <cuda_fp16.h>
#include <cstdint>
#include <math.h>

// ---------------------------------------------------------------------------
// Problem constants
// ---------------------------------------------------------------------------
#define B_ 4
#define L_ 2048
#define D_ 256
#define H_ 4096
#define M_ (B_ * L_)          // 8192
#define CHUNK_ 128
#define NC_ (L_ / CHUNK_)     // 16

// ---------------------------------------------------------------------------
// Scratch (device globals; no allocation allowed)
// g_b holds b [M,H] fp32 for the scan; dead after phaseC, so GEMM2's split-K
// partials (2 x M x D fp32) reuse its space.
// ---------------------------------------------------------------------------
__device__ __align__(256) float  g_b[(size_t)M_ * H_];      // 128 MB
__device__ __align__(256) __half g_hhi[(size_t)M_ * H_];
__device__ __align__(256) __half g_hlo[(size_t)M_ * H_];
__device__ __align__(256) __half g_xhi[(size_t)M_ * D_];
__device__ __align__(256) __half g_xlo[(size_t)M_ * D_];
__device__ __align__(256) __half g_wbh[(size_t)H_ * D_];
__device__ __align__(256) __half g_wch[(size_t)D_ * H_];
__device__ __align__(256) float  g_carry[B_ * NC_ * H_];
__device__ __align__(256) float  g_hprev[B_ * NC_ * H_];

// ---------------------------------------------------------------------------
// PTX helpers (baseline ISA only: cp.async / ldmatrix / mma.sync)
// ---------------------------------------------------------------------------
__device__ __forceinline__ uint32_t smem_to_u32(const void* p) {
    uint32_t a;
    asm("{ .reg .u64 t; cvta.to.shared.u64 t, %1; cvt.u32.u64 %0, t; }" : "=r"(a) : "l"(p));
    return a;
}
__device__ __forceinline__ void cp_async16(uint32_t dst, const void* src) {
    asm volatile("cp.async.cg.shared.global [%0], [%1], 16;" :: "r"(dst), "l"(src) : "memory");
}
__device__ __forceinline__ void cp_commit() {
    asm volatile("cp.async.commit_group;" ::: "memory");
}
__device__ __forceinline__ void cp_wait2() {
    asm volatile("cp.async.wait_group 2;" ::: "memory");
}
__device__ __forceinline__ void ldsm_x4(uint32_t* r, uint32_t addr) {
    asm volatile("ldmatrix.sync.aligned.m8n8.x4.shared.b16 {%0,%1,%2,%3}, [%4];"
                 : "=r"(r[0]), "=r"(r[1]), "=r"(r[2]), "=r"(r[3]) : "r"(addr));
}
__device__ __forceinline__ void mma_f16(float* c, const uint32_t* a, const uint32_t* b) {
    asm volatile(
        "mma.sync.aligned.m16n8k16.row.col.f32.f16.f16.f32 "
        "{%0,%1,%2,%3}, {%4,%5,%6,%7}, {%8,%9}, {%0,%1,%2,%3};"
        : "+f"(c[0]), "+f"(c[1]), "+f"(c[2]), "+f"(c[3])
        : "r"(a[0]), "r"(a[1]), "r"(a[2]), "r"(a[3]), "r"(b[0]), "r"(b[1]));
}

// Swizzle: 64B rows, 4x 16B lanes; lane ^= (row%4) ^ ((row/4)%4)
__device__ __forceinline__ uint32_t sw_off(int row, int lane) {
    return (uint32_t)(row * 64 + ((lane ^ (row & 3) ^ ((row >> 2) & 3)) << 4));
}

__device__ __forceinline__ float dsigmoid(float x) { return 1.0f / (1.0f + expf(-x)); }

// ---------------------------------------------------------------------------
// Split fp32 -> (hi, lo) fp16;  and plain fp32 -> fp16 convert
// ---------------------------------------------------------------------------
__global__ void split_f32_h(const float* __restrict__ src,
                            __half* __restrict__ hi, __half* __restrict__ lo, int n4)
{
    int i = blockIdx.x * blockDim.x + threadIdx.x;
    if (i >= n4) return;
    float4 v = reinterpret_cast<const float4*>(src)[i];
    __half h0 = __float2half_rn(v.x), h1 = __float2half_rn(v.y);
    __half h2 = __float2half_rn(v.z), h3 = __float2half_rn(v.w);
    __half l0 = __float2half_rn(v.x - __half2float(h0));
    __half l1 = __float2half_rn(v.y - __half2float(h1));
    __half l2 = __float2half_rn(v.z - __half2float(h2));
    __half l3 = __float2half_rn(v.w - __half2float(h3));
    reinterpret_cast<__half2*>(hi)[2 * i + 0] = __halves2half2(h0, h1);
    reinterpret_cast<__half2*>(hi)[2 * i + 1] = __halves2half2(h2, h3);
    reinterpret_cast<__half2*>(lo)[2 * i + 0] = __halves2half2(l0, l1);
    reinterpret_cast<__half2*>(lo)[2 * i + 1] = __halves2half2(l2, l3);
}

__global__ void conv_f32_h(const float* __restrict__ src, __half* __restrict__ dst, int n4)
{
    int i = blockIdx.x * blockDim.x + threadIdx.x;
    if (i >= n4) return;
    float4 v = reinterpret_cast<const float4*>(src)[i];
    reinterpret_cast<__half2*>(dst)[2 * i + 0] = __halves2half2(__float2half_rn(v.x), __float2half_rn(v.y));
    reinterpret_cast<__half2*>(dst)[2 * i + 1] = __halves2half2(__float2half_rn(v.z), __float2half_rn(v.w));
}

// ---------------------------------------------------------------------------
// fp16 2-stream GEMM (NT) via mma.sync:
//   C[M,N] (+)= (Ahi+Alo)[M,Klen] @ (Bw[N,Klen])^T (+ bias[N])
// BM=128, BN=128, BK=32; 8 warps (4m x 2n), warp tile 32x64.
// 4-stage cp.async pipeline; 24KB/stage -> 96KB smem -> 2 CTAs/SM.
// ---------------------------------------------------------------------------
#define BM_ 128
#define BN_ 128
#define BK_ 32
#define NSTAGE_ 4
#define STG_ 24576
#define T_AHI 0
#define T_ALO 8192
#define T_B   16384

__device__ __forceinline__ void load_stage(
    uint32_t st, int tid, const char* Ahi, const char* Alo, const char* Bw,
    size_t rowbytes, int bm, int bn, int k0byte)
{
#pragma unroll
    for (int i = 0; i < 2; i++) {
        int l = tid + i * 256;          // 0..511 lanes of 16B
        int r = l >> 2, c = l & 3;
        uint32_t sw = sw_off(r, c);
        size_t ga = (size_t)(bm + r) * rowbytes + k0byte + c * 16;
        size_t gb = (size_t)(bn + r) * rowbytes + k0byte + c * 16;
        cp_async16(st + T_AHI + sw, Ahi + ga);
        cp_async16(st + T_ALO + sw, Alo + ga);
        cp_async16(st + T_B + sw, Bw + gb);
    }
}

__global__ __launch_bounds__(256, 2)
void gemm_fp16s2(const __half* __restrict__ Ahi, const __half* __restrict__ Alo,
                 const __half* __restrict__ Bw,
                 const float* __restrict__ bias, float* __restrict__ C,
                 int N, int K, int Klen, size_t zstride)
{
    extern __shared__ char smem[];
    const uint32_t sb = smem_to_u32(smem);
    const int tid = threadIdx.x;
    const int wid = tid >> 5, lid = tid & 31;
    const int wm = wid & 3, wn = wid >> 2;        // 4(m) x 2(n) warp grid
    const int bm = blockIdx.y * BM_;
    const int bn = blockIdx.x * BN_;
    const size_t rowbytes = (size_t)K * 2;
    const int NKC = Klen / BK_;
    const size_t kofs = (size_t)blockIdx.z * Klen * 2;

    const char* pAh = (const char*)Ahi + kofs;
    const char* pAl = (const char*)Alo + kofs;
    const char* pB  = (const char*)Bw + kofs;
    C += (size_t)blockIdx.z * zstride;

    float acc[2][8][4];
#pragma unroll
    for (int mt = 0; mt < 2; mt++)
#pragma unroll
        for (int nt = 0; nt < 8; nt++)
#pragma unroll
            for (int j = 0; j < 4; j++) acc[mt][nt][j] = 0.0f;

    // Prologue: stages 0..2
#pragma unroll
    for (int s = 0; s < NSTAGE_ - 1; s++) {
        if (s < NKC) load_stage(sb + s * STG_, tid, pAh, pAl, pB, rowbytes, bm, bn, s * BK_ * 2);
        cp_commit();
    }

#pragma unroll 1
    for (int kc = 0; kc < NKC; kc++) {
        cp_wait2();
        __syncthreads();
        {
            int nx = kc + NSTAGE_ - 1;
            if (nx < NKC)
                load_stage(sb + (nx % NSTAGE_) * STG_, tid, pAh, pAl, pB, rowbytes, bm, bn, nx * BK_ * 2);
            cp_commit();
        }
        const uint32_t st = sb + (kc % NSTAGE_) * STG_;

#pragma unroll
        for (int kst = 0; kst < 2; kst++) {
            uint32_t ah[2][4], al[2][4], bw[4][4];
#pragma unroll
            for (int mt = 0; mt < 2; mt++) {
                int row = wm * 32 + mt * 16 + (lid & 15);
                int lane = kst * 2 + (lid >> 4);
                uint32_t off = sw_off(row, lane);
                ldsm_x4(ah[mt], st + T_AHI + off);
                ldsm_x4(al[mt], st + T_ALO + off);
            }
#pragma unroll
            for (int nt2 = 0; nt2 < 4; nt2++) {
                int row = wn * 64 + nt2 * 16 + (lid & 7) + ((lid >> 4) << 3);
                int lane = kst * 2 + ((lid >> 3) & 1);
                uint32_t off = sw_off(row, lane);
                ldsm_x4(bw[nt2], st + T_B + off);
            }
            // 2 streams: hi*B x16, lo*B x16
#pragma unroll
            for (int mt = 0; mt < 2; mt++)
#pragma unroll
                for (int nt = 0; nt < 8; nt++)
                    mma_f16(acc[mt][nt], ah[mt], &bw[nt >> 1][(nt & 1) * 2]);
#pragma unroll
            for (int mt = 0; mt < 2; mt++)
#pragma unroll
                for (int nt = 0; nt < 8; nt++)
                    mma_f16(acc[mt][nt], al[mt], &bw[nt >> 1][(nt & 1) * 2]);
        }
        __syncthreads();
    }

    // Epilogue: add bias (if any), store fp32
    const int r0 = bm + wm * 32 + (lid >> 2);
    const int cq = (lid & 3) * 2;
#pragma unroll
    for (int mt = 0; mt < 2; mt++) {
#pragma unroll
        for (int nt = 0; nt < 8; nt++) {
            int col = bn + wn * 64 + nt * 8 + cq;
            float bx = 0.0f, by = 0.0f;
            if (bias) { bx = bias[col]; by = bias[col + 1]; }
            float2 v0 = make_float2(acc[mt][nt][0] + bx, acc[mt][nt][1] + by);
            float2 v1 = make_float2(acc[mt][nt][2] + bx, acc[mt][nt][3] + by);
            *reinterpret_cast<float2*>(&C[(size_t)(r0 + mt * 16) * N + col]) = v0;
            *reinterpret_cast<float2*>(&C[(size_t)(r0 + mt * 16 + 8) * N + col]) = v1;
        }
    }
}

// Split-K reduce: out[i] = p0[i] + p1[i] + bias[col]
__global__ void reduce_splitk(const float* __restrict__ part, const float* __restrict__ bias,
                              float* __restrict__ out, int n4, size_t zstride4, int Nmask4)
{
    int i = blockIdx.x * blockDim.x + threadIdx.x;
    if (i >= n4) return;
    float4 a = reinterpret_cast<const float4*>(part)[i];
    float4 b = reinterpret_cast<const float4*>(part)[i + zstride4];
    int col = (i & Nmask4) * 4;
    float4 v;
    v.x = a.x + b.x + bias[col + 0];
    v.y = a.y + b.y + bias[col + 1];
    v.z = a.z + b.z + bias[col + 2];
    v.w = a.w + b.w + bias[col + 3];
    reinterpret_cast<float4*>(out)[i] = v;
}

// ---------------------------------------------------------------------------
// Scan:  h_t = a*h_{t-1} + b_t, a = sigmoid(A[h]); chunked over L
// ---------------------------------------------------------------------------
__global__ void scan_reduceA(const float* __restrict__ bbuf, const float* __restrict__ Araw,
                             float* __restrict__ carry)
{
    int idx = blockIdx.x * blockDim.x + threadIdx.x;   // [B, NC, H]
    int h = idx & (H_ - 1);
    int c = (idx >> 12) & (NC_ - 1);
    int bb = idx >> 16;
    float a = dsigmoid(Araw[h]);
    size_t base = ((size_t)bb * L_ + (size_t)c * CHUNK_) * H_ + h;
    float s = 0.0f;
#pragma unroll 8
    for (int i = 0; i < CHUNK_; i++) s = fmaf(a, s, bbuf[base + (size_t)i * H_]);
    carry[idx] = s;
}

__global__ void scan_phaseB(const float* __restrict__ carry, const float* __restrict__ Araw,
                            float* __restrict__ hprev)
{
    int idx = blockIdx.x * blockDim.x + threadIdx.x;   // [B, H]
    int h = idx & (H_ - 1);
    int bb = idx >> 12;
    float a = dsigmoid(Araw[h]);
    float aC = a;
#pragma unroll
    for (int i = 0; i < 7; i++) aC *= aC;              // a^128
    float run = 0.0f;
#pragma unroll
    for (int c = 0; c < NC_; c++) {
        size_t off = ((size_t)bb * NC_ + c) * H_ + h;
        hprev[off] = run;
        run = fmaf(aC, run, carry[off]);
    }
}

__global__ void scan_phaseC(const float* __restrict__ bbuf, const float* __restrict__ Araw,
                            const float* __restrict__ hprev,
                            __half* __restrict__ hhi, __half* __restrict__ hlo)
{
    int idx = blockIdx.x * blockDim.x + threadIdx.x;   // [B, NC, H]
    int h = idx & (H_ - 1);
    int c = (idx >> 12) & (NC_ - 1);
    int bb = idx >> 16;
    float a = dsigmoid(Araw[h]);
    float Hp = hprev[idx];
    size_t base = ((size_t)bb * L_ + (size_t)c * CHUNK_) * H_ + h;
    float s = 0.0f, p = 1.0f;
#pragma unroll 8
    for (int i = 0; i < CHUNK_; i++) {
        size_t off = base + (size_t)i * H_;
        p *= a;                        // a^(i+1)
        s = fmaf(a, s, bbuf[off]);     // local inclusive scan
        float v = fmaf(p, Hp, s);      // + carry-in contribution
        __half hi = __float2half_rn(v);
        hhi[off] = hi;
        hlo[off] = __float2half_rn(v - __half2float(hi));
    }
}

// ---------------------------------------------------------------------------
extern "C" void kernel_launch(void* const* d_in, const int* in_sizes, int n_in,
                              void* d_out, int out_size)
{
    const float* x  = (const float*)d_in[0];   // [B, L, D]
    const float* WB = (const float*)d_in[1];   // [H, D]
    const float* bB = (const float*)d_in[2];   // [H]
    const float* WC = (const float*)d_in[3];   // [D, H]
    const float* bC = (const float*)d_in[4];   // [D]
    const float* A  = (const float*)d_in[5];   // [H]
    float* out = (float*)d_out;                // [B, L, D]

    float *bbuf, *carry, *hprev;
    __half *xhi, *xlo, *wbh, *wch, *hhi, *hlo;
    cudaGetSymbolAddress((void**)&bbuf, g_b);
    cudaGetSymbolAddress((void**)&carry, g_carry);
    cudaGetSymbolAddress((void**)&hprev, g_hprev);
    cudaGetSymbolAddress((void**)&xhi, g_xhi);
    cudaGetSymbolAddress((void**)&xlo, g_xlo);
    cudaGetSymbolAddress((void**)&wbh, g_wbh);
    cudaGetSymbolAddress((void**)&wch, g_wch);
    cudaGetSymbolAddress((void**)&hhi, g_hhi);
    cudaGetSymbolAddress((void**)&hlo, g_hlo);

    const int SMEM_G = NSTAGE_ * STG_;     // 96 KB -> 2 CTAs/SM
    cudaFuncSetAttribute(gemm_fp16s2, cudaFuncAttributeMaxDynamicSharedMemorySize, SMEM_G);

    // Convert inputs
    split_f32_h<<<(M_ * D_ / 4 + 255) / 256, 256>>>(x, xhi, xlo, M_ * D_ / 4);
    conv_f32_h<<<(H_ * D_ / 4 + 255) / 256, 256>>>(WB, wbh, H_ * D_ / 4);
    conv_f32_h<<<(D_ * H_ / 4 + 255) / 256, 256>>>(WC, wch, D_ * H_ / 4);

    // GEMM1: b = x @ WB^T + bB   (M=8192, N=4096, K=256)
    gemm_fp16s2<<<dim3(H_ / BN_, M_ / BM_, 1), 256, SMEM_G>>>(
        xhi, xlo, wbh, bB, bbuf, H_, D_, D_, 0);

    // Scan over L
    scan_reduceA<<<(B_ * NC_ * H_) / 256, 256>>>(bbuf, A, carry);
    scan_phaseB<<<(B_ * H_) / 256, 256>>>(carry, A, hprev);
    scan_phaseC<<<(B_ * NC_ * H_) / 256, 256>>>(bbuf, A, hprev, hhi, hlo);

    // GEMM2: out = h @ WC^T + bC  (M=8192, N=256, K=4096), split-K=2.
    const size_t zstride = (size_t)M_ * D_;
    gemm_fp16s2<<<dim3(D_ / BN_, M_ / BM_, 2), 256, SMEM_G>>>(
        hhi, hlo, wch, nullptr, bbuf, D_, H_, H_ / 2, zstride);
    reduce_splitk<<<(M_ * D_ / 4 + 255) / 256, 256>>>(
        bbuf, bC, out, M_ * D_ / 4, zstride / 4, (D_ / 4) - 1);
}

// round 9
// speedup vs baseline: 2.9359x; 1.4220x over previous
#include <cuda_runtime.h>
#include <cuda_fp16.h>
#include <cstdint>
#include <math.h>

// ---------------------------------------------------------------------------
// Problem constants
// ---------------------------------------------------------------------------
#define B_ 4
#define L_ 2048
#define D_ 256
#define H_ 4096
#define M_ (B_ * L_)          // 8192
#define CHUNK_ 128
#define NC_ (L_ / CHUNK_)     // 16

// ---------------------------------------------------------------------------
// Scratch (device globals; no allocation allowed)
// g_b holds b [M,H] fp32 for the scan; dead after phaseC, so GEMM2's split-K
// partials (2 x M x D fp32) reuse its space.
// ---------------------------------------------------------------------------
__device__ __align__(256) float  g_b[(size_t)M_ * H_];      // 128 MB
__device__ __align__(256) __half g_hh[(size_t)M_ * H_];     // h fp16
__device__ __align__(256) __half g_xh[(size_t)M_ * D_];
__device__ __align__(256) __half g_wbh[(size_t)H_ * D_];
__device__ __align__(256) __half g_wch[(size_t)D_ * H_];
__device__ __align__(256) float  g_carry[B_ * NC_ * H_];
__device__ __align__(256) float  g_hprev[B_ * NC_ * H_];

// ---------------------------------------------------------------------------
// PTX helpers (baseline ISA only: cp.async / ldmatrix / mma.sync)
// ---------------------------------------------------------------------------
__device__ __forceinline__ uint32_t smem_to_u32(const void* p) {
    uint32_t a;
    asm("{ .reg .u64 t; cvta.to.shared.u64 t, %1; cvt.u32.u64 %0, t; }" : "=r"(a) : "l"(p));
    return a;
}
__device__ __forceinline__ void cp_async16(uint32_t dst, const void* src) {
    asm volatile("cp.async.cg.shared.global [%0], [%1], 16;" :: "r"(dst), "l"(src) : "memory");
}
__device__ __forceinline__ void cp_commit() {
    asm volatile("cp.async.commit_group;" ::: "memory");
}
__device__ __forceinline__ void cp_wait4() {
    asm volatile("cp.async.wait_group 4;" ::: "memory");
}
__device__ __forceinline__ void ldsm_x4(uint32_t* r, uint32_t addr) {
    asm volatile("ldmatrix.sync.aligned.m8n8.x4.shared.b16 {%0,%1,%2,%3}, [%4];"
                 : "=r"(r[0]), "=r"(r[1]), "=r"(r[2]), "=r"(r[3]) : "r"(addr));
}
__device__ __forceinline__ void mma_f16(float* c, const uint32_t* a, const uint32_t* b) {
    asm volatile(
        "mma.sync.aligned.m16n8k16.row.col.f32.f16.f16.f32 "
        "{%0,%1,%2,%3}, {%4,%5,%6,%7}, {%8,%9}, {%0,%1,%2,%3};"
        : "+f"(c[0]), "+f"(c[1]), "+f"(c[2]), "+f"(c[3])
        : "r"(a[0]), "r"(a[1]), "r"(a[2]), "r"(a[3]), "r"(b[0]), "r"(b[1]));
}

// Swizzle: 64B rows, 4x 16B lanes; lane ^= (row%4) ^ ((row/4)%4)
__device__ __forceinline__ uint32_t sw_off(int row, int lane) {
    return (uint32_t)(row * 64 + ((lane ^ (row & 3) ^ ((row >> 2) & 3)) << 4));
}

__device__ __forceinline__ float dsigmoid(float x) { return 1.0f / (1.0f + expf(-x)); }

// ---------------------------------------------------------------------------
// fp32 -> fp16 convert
// ---------------------------------------------------------------------------
__global__ void conv_f32_h(const float* __restrict__ src, __half* __restrict__ dst, int n4)
{
    int i = blockIdx.x * blockDim.x + threadIdx.x;
    if (i >= n4) return;
    float4 v = reinterpret_cast<const float4*>(src)[i];
    reinterpret_cast<__half2*>(dst)[2 * i + 0] = __halves2half2(__float2half_rn(v.x), __float2half_rn(v.y));
    reinterpret_cast<__half2*>(dst)[2 * i + 1] = __halves2half2(__float2half_rn(v.z), __float2half_rn(v.w));
}

// ---------------------------------------------------------------------------
// Single-stream fp16 GEMM (NT) via mma.sync:
//   C[M,N] (+)= Aw[M,Klen] @ (Bw[N,Klen])^T (+ bias[N])
// BM=128, BN=128, BK=32; 8 warps (4m x 2n), warp tile 32x64.
// 6-stage cp.async pipeline; 16KB/stage -> 96KB smem -> 2 CTAs/SM.
// ---------------------------------------------------------------------------
#define BM_ 128
#define BN_ 128
#define BK_ 32
#define NSTAGE_ 6
#define STG_ 16384
#define T_A 0
#define T_B 8192

__device__ __forceinline__ void load_stage(
    uint32_t st, int tid, const char* Aw, const char* Bw,
    size_t rowbytes, int bm, int bn, int k0byte)
{
#pragma unroll
    for (int i = 0; i < 2; i++) {
        int l = tid + i * 256;          // 0..511 lanes of 16B
        int r = l >> 2, c = l & 3;
        uint32_t sw = sw_off(r, c);
        size_t ga = (size_t)(bm + r) * rowbytes + k0byte + c * 16;
        size_t gb = (size_t)(bn + r) * rowbytes + k0byte + c * 16;
        cp_async16(st + T_A + sw, Aw + ga);
        cp_async16(st + T_B + sw, Bw + gb);
    }
}

__global__ __launch_bounds__(256, 2)
void gemm_fp16(const __half* __restrict__ Aw, const __half* __restrict__ Bw,
               const float* __restrict__ bias, float* __restrict__ C,
               int N, int K, int Klen, size_t zstride)
{
    extern __shared__ char smem[];
    const uint32_t sb = smem_to_u32(smem);
    const int tid = threadIdx.x;
    const int wid = tid >> 5, lid = tid & 31;
    const int wm = wid & 3, wn = wid >> 2;        // 4(m) x 2(n) warp grid
    const int bm = blockIdx.y * BM_;
    const int bn = blockIdx.x * BN_;
    const size_t rowbytes = (size_t)K * 2;
    const int NKC = Klen / BK_;
    const size_t kofs = (size_t)blockIdx.z * Klen * 2;

    const char* pA = (const char*)Aw + kofs;
    const char* pB = (const char*)Bw + kofs;
    C += (size_t)blockIdx.z * zstride;

    float acc[2][8][4];
#pragma unroll
    for (int mt = 0; mt < 2; mt++)
#pragma unroll
        for (int nt = 0; nt < 8; nt++)
#pragma unroll
            for (int j = 0; j < 4; j++) acc[mt][nt][j] = 0.0f;

    // Prologue: stages 0..4
#pragma unroll
    for (int s = 0; s < NSTAGE_ - 1; s++) {
        if (s < NKC) load_stage(sb + s * STG_, tid, pA, pB, rowbytes, bm, bn, s * BK_ * 2);
        cp_commit();
    }

#pragma unroll 1
    for (int kc = 0; kc < NKC; kc++) {
        cp_wait4();
        __syncthreads();
        {
            int nx = kc + NSTAGE_ - 1;
            if (nx < NKC)
                load_stage(sb + (nx % NSTAGE_) * STG_, tid, pA, pB, rowbytes, bm, bn, nx * BK_ * 2);
            cp_commit();
        }
        const uint32_t st = sb + (kc % NSTAGE_) * STG_;

#pragma unroll
        for (int kst = 0; kst < 2; kst++) {
            uint32_t af[2][4], bf[4][4];
#pragma unroll
            for (int mt = 0; mt < 2; mt++) {
                int row = wm * 32 + mt * 16 + (lid & 15);
                int lane = kst * 2 + (lid >> 4);
                ldsm_x4(af[mt], st + T_A + sw_off(row, lane));
            }
#pragma unroll
            for (int nt2 = 0; nt2 < 4; nt2++) {
                int row = wn * 64 + nt2 * 16 + (lid & 7) + ((lid >> 4) << 3);
                int lane = kst * 2 + ((lid >> 3) & 1);
                ldsm_x4(bf[nt2], st + T_B + sw_off(row, lane));
            }
#pragma unroll
            for (int mt = 0; mt < 2; mt++)
#pragma unroll
                for (int nt = 0; nt < 8; nt++)
                    mma_f16(acc[mt][nt], af[mt], &bf[nt >> 1][(nt & 1) * 2]);
        }
        __syncthreads();
    }

    // Epilogue: add bias (if any), store fp32
    const int r0 = bm + wm * 32 + (lid >> 2);
    const int cq = (lid & 3) * 2;
#pragma unroll
    for (int mt = 0; mt < 2; mt++) {
#pragma unroll
        for (int nt = 0; nt < 8; nt++) {
            int col = bn + wn * 64 + nt * 8 + cq;
            float bx = 0.0f, by = 0.0f;
            if (bias) { bx = bias[col]; by = bias[col + 1]; }
            float2 v0 = make_float2(acc[mt][nt][0] + bx, acc[mt][nt][1] + by);
            float2 v1 = make_float2(acc[mt][nt][2] + bx, acc[mt][nt][3] + by);
            *reinterpret_cast<float2*>(&C[(size_t)(r0 + mt * 16) * N + col]) = v0;
            *reinterpret_cast<float2*>(&C[(size_t)(r0 + mt * 16 + 8) * N + col]) = v1;
        }
    }
}

// Split-K reduce: out[i] = p0[i] + p1[i] + bias[col]
__global__ void reduce_splitk(const float* __restrict__ part, const float* __restrict__ bias,
                              float* __restrict__ out, int n4, size_t zstride4, int Nmask4)
{
    int i = blockIdx.x * blockDim.x + threadIdx.x;
    if (i >= n4) return;
    float4 a = reinterpret_cast<const float4*>(part)[i];
    float4 b = reinterpret_cast<const float4*>(part)[i + zstride4];
    int col = (i & Nmask4) * 4;
    float4 v;
    v.x = a.x + b.x + bias[col + 0];
    v.y = a.y + b.y + bias[col + 1];
    v.z = a.z + b.z + bias[col + 2];
    v.w = a.w + b.w + bias[col + 3];
    reinterpret_cast<float4*>(out)[i] = v;
}

// ---------------------------------------------------------------------------
// Scan:  h_t = a*h_{t-1} + b_t, a = sigmoid(A[h]); chunked over L
// ---------------------------------------------------------------------------
__global__ void scan_reduceA(const float* __restrict__ bbuf, const float* __restrict__ Araw,
                             float* __restrict__ carry)
{
    int idx = blockIdx.x * blockDim.x + threadIdx.x;   // [B, NC, H]
    int h = idx & (H_ - 1);
    int c = (idx >> 12) & (NC_ - 1);
    int bb = idx >> 16;
    float a = dsigmoid(Araw[h]);
    size_t base = ((size_t)bb * L_ + (size_t)c * CHUNK_) * H_ + h;
    float s = 0.0f;
#pragma unroll 8
    for (int i = 0; i < CHUNK_; i++) s = fmaf(a, s, bbuf[base + (size_t)i * H_]);
    carry[idx] = s;
}

__global__ void scan_phaseB(const float* __restrict__ carry, const float* __restrict__ Araw,
                            float* __restrict__ hprev)
{
    int idx = blockIdx.x * blockDim.x + threadIdx.x;   // [B, H]
    int h = idx & (H_ - 1);
    int bb = idx >> 12;
    float a = dsigmoid(Araw[h]);
    float aC = a;
#pragma unroll
    for (int i = 0; i < 7; i++) aC *= aC;              // a^128
    float run = 0.0f;
#pragma unroll
    for (int c = 0; c < NC_; c++) {
        size_t off = ((size_t)bb * NC_ + c) * H_ + h;
        hprev[off] = run;
        run = fmaf(aC, run, carry[off]);
    }
}

__global__ void scan_phaseC(const float* __restrict__ bbuf, const float* __restrict__ Araw,
                            const float* __restrict__ hprev,
                            __half* __restrict__ hh)
{
    int idx = blockIdx.x * blockDim.x + threadIdx.x;   // [B, NC, H]
    int h = idx & (H_ - 1);
    int c = (idx >> 12) & (NC_ - 1);
    int bb = idx >> 16;
    float a = dsigmoid(Araw[h]);
    float Hp = hprev[idx];
    size_t base = ((size_t)bb * L_ + (size_t)c * CHUNK_) * H_ + h;
    float s = 0.0f, p = 1.0f;
#pragma unroll 8
    for (int i = 0; i < CHUNK_; i++) {
        size_t off = base + (size_t)i * H_;
        p *= a;                        // a^(i+1)
        s = fmaf(a, s, bbuf[off]);     // local inclusive scan
        float v = fmaf(p, Hp, s);      // + carry-in contribution
        hh[off] = __float2half_rn(v);
    }
}

// ---------------------------------------------------------------------------
extern "C" void kernel_launch(void* const* d_in, const int* in_sizes, int n_in,
                              void* d_out, int out_size)
{
    const float* x  = (const float*)d_in[0];   // [B, L, D]
    const float* WB = (const float*)d_in[1];   // [H, D]
    const float* bB = (const float*)d_in[2];   // [H]
    const float* WC = (const float*)d_in[3];   // [D, H]
    const float* bC = (const float*)d_in[4];   // [D]
    const float* A  = (const float*)d_in[5];   // [H]
    float* out = (float*)d_out;                // [B, L, D]

    float *bbuf, *carry, *hprev;
    __half *xh, *wbh, *wch, *hh;
    cudaGetSymbolAddress((void**)&bbuf, g_b);
    cudaGetSymbolAddress((void**)&carry, g_carry);
    cudaGetSymbolAddress((void**)&hprev, g_hprev);
    cudaGetSymbolAddress((void**)&xh, g_xh);
    cudaGetSymbolAddress((void**)&wbh, g_wbh);
    cudaGetSymbolAddress((void**)&wch, g_wch);
    cudaGetSymbolAddress((void**)&hh, g_hh);

    const int SMEM_G = NSTAGE_ * STG_;     // 96 KB -> 2 CTAs/SM
    cudaFuncSetAttribute(gemm_fp16, cudaFuncAttributeMaxDynamicSharedMemorySize, SMEM_G);

    // Convert inputs to fp16
    conv_f32_h<<<(M_ * D_ / 4 + 255) / 256, 256>>>(x, xh, M_ * D_ / 4);
    conv_f32_h<<<(H_ * D_ / 4 + 255) / 256, 256>>>(WB, wbh, H_ * D_ / 4);
    conv_f32_h<<<(D_ * H_ / 4 + 255) / 256, 256>>>(WC, wch, D_ * H_ / 4);

    // GEMM1: b = x @ WB^T + bB   (M=8192, N=4096, K=256)
    gemm_fp16<<<dim3(H_ / BN_, M_ / BM_, 1), 256, SMEM_G>>>(
        xh, wbh, bB, bbuf, H_, D_, D_, 0);

    // Scan over L
    scan_reduceA<<<(B_ * NC_ * H_) / 256, 256>>>(bbuf, A, carry);
    scan_phaseB<<<(B_ * H_) / 256, 256>>>(carry, A, hprev);
    scan_phaseC<<<(B_ * NC_ * H_) / 256, 256>>>(bbuf, A, hprev, hh);

    // GEMM2: out = h @ WC^T + bC  (M=8192, N=256, K=4096), split-K=2.
    const size_t zstride = (size_t)M_ * D_;
    gemm_fp16<<<dim3(D_ / BN_, M_ / BM_, 2), 256, SMEM_G>>>(
        hh, wch, nullptr, bbuf, D_, H_, H_ / 2, zstride);
    reduce_splitk<<<(M_ * D_ / 4 + 255) / 256, 256>>>(
        bbuf, bC, out, M_ * D_ / 4, zstride / 4, (D_ / 4) - 1);
}

// round 10
// speedup vs baseline: 3.2176x; 1.0959x over previous
#include <cuda_runtime.h>
#include <cuda_fp16.h>
#include <cstdint>
#include <math.h>

// ---------------------------------------------------------------------------
// Problem constants
// ---------------------------------------------------------------------------
#define B_ 4
#define L_ 2048
#define D_ 256
#define H_ 4096
#define M_ (B_ * L_)          // 8192
#define CHUNK_ 128
#define NC_ (L_ / CHUNK_)     // 16

// ---------------------------------------------------------------------------
// Scratch (device globals; no allocation allowed)
// g_b front 64MB: b fp16 [M,H]. Back region (offset 16M floats): GEMM2
// split-K fp32 partials (2 x M x D). Disjoint lifetimes guaranteed by layout.
// ---------------------------------------------------------------------------
__device__ __align__(256) float  g_b[(size_t)M_ * H_];      // 128 MB arena
__device__ __align__(256) __half g_hh[(size_t)M_ * H_];     // h fp16
__device__ __align__(256) __half g_xh[(size_t)M_ * D_];
__device__ __align__(256) __half g_wbh[(size_t)H_ * D_];
__device__ __align__(256) __half g_wch[(size_t)D_ * H_];
__device__ __align__(256) float  g_carry[B_ * NC_ * H_];
__device__ __align__(256) float  g_hprev[B_ * NC_ * H_];

// ---------------------------------------------------------------------------
// PTX helpers (baseline ISA only: cp.async / ldmatrix / mma.sync)
// ---------------------------------------------------------------------------
__device__ __forceinline__ uint32_t smem_to_u32(const void* p) {
    uint32_t a;
    asm("{ .reg .u64 t; cvta.to.shared.u64 t, %1; cvt.u32.u64 %0, t; }" : "=r"(a) : "l"(p));
    return a;
}
__device__ __forceinline__ void cp_async16(uint32_t dst, const void* src) {
    asm volatile("cp.async.cg.shared.global [%0], [%1], 16;" :: "r"(dst), "l"(src) : "memory");
}
__device__ __forceinline__ void cp_commit() {
    asm volatile("cp.async.commit_group;" ::: "memory");
}
__device__ __forceinline__ void cp_wait4() {
    asm volatile("cp.async.wait_group 4;" ::: "memory");
}
__device__ __forceinline__ void ldsm_x4(uint32_t* r, uint32_t addr) {
    asm volatile("ldmatrix.sync.aligned.m8n8.x4.shared.b16 {%0,%1,%2,%3}, [%4];"
                 : "=r"(r[0]), "=r"(r[1]), "=r"(r[2]), "=r"(r[3]) : "r"(addr));
}
__device__ __forceinline__ void mma_f16(float* c, const uint32_t* a, const uint32_t* b) {
    asm volatile(
        "mma.sync.aligned.m16n8k16.row.col.f32.f16.f16.f32 "
        "{%0,%1,%2,%3}, {%4,%5,%6,%7}, {%8,%9}, {%0,%1,%2,%3};"
        : "+f"(c[0]), "+f"(c[1]), "+f"(c[2]), "+f"(c[3])
        : "r"(a[0]), "r"(a[1]), "r"(a[2]), "r"(a[3]), "r"(b[0]), "r"(b[1]));
}

// Swizzle: 64B rows, 4x 16B lanes; lane ^= (row%4) ^ ((row/4)%4)
__device__ __forceinline__ uint32_t sw_off(int row, int lane) {
    return (uint32_t)(row * 64 + ((lane ^ (row & 3) ^ ((row >> 2) & 3)) << 4));
}

__device__ __forceinline__ float dsigmoid(float x) { return 1.0f / (1.0f + expf(-x)); }

// Output store helpers
__device__ __forceinline__ void store2(float* C, size_t off, float vx, float vy) {
    *reinterpret_cast<float2*>(C + off) = make_float2(vx, vy);
}
__device__ __forceinline__ void store2(__half* C, size_t off, float vx, float vy) {
    *reinterpret_cast<__half2*>(C + off) = __floats2half2_rn(vx, vy);
}

// ---------------------------------------------------------------------------
// fp32 -> fp16 convert
// ---------------------------------------------------------------------------
__global__ void conv_f32_h(const float* __restrict__ src, __half* __restrict__ dst, int n4)
{
    int i = blockIdx.x * blockDim.x + threadIdx.x;
    if (i >= n4) return;
    float4 v = reinterpret_cast<const float4*>(src)[i];
    reinterpret_cast<__half2*>(dst)[2 * i + 0] = __halves2half2(__float2half_rn(v.x), __float2half_rn(v.y));
    reinterpret_cast<__half2*>(dst)[2 * i + 1] = __halves2half2(__float2half_rn(v.z), __float2half_rn(v.w));
}

// ---------------------------------------------------------------------------
// Single-stream fp16 GEMM (NT) via mma.sync, templated output type:
//   C[M,N] (+)= Aw[M,Klen] @ (Bw[N,Klen])^T (+ bias[N])
// BM=128, BN=128, BK=32; 8 warps (4m x 2n), warp tile 32x64.
// 6-stage cp.async pipeline; 16KB/stage -> 96KB smem -> 2 CTAs/SM.
// ---------------------------------------------------------------------------
#define BM_ 128
#define BN_ 128
#define BK_ 32
#define NSTAGE_ 6
#define STG_ 16384
#define T_A 0
#define T_B 8192

__device__ __forceinline__ void load_stage(
    uint32_t st, int tid, const char* Aw, const char* Bw,
    size_t rowbytes, int bm, int bn, int k0byte)
{
#pragma unroll
    for (int i = 0; i < 2; i++) {
        int l = tid + i * 256;          // 0..511 lanes of 16B
        int r = l >> 2, c = l & 3;
        uint32_t sw = sw_off(r, c);
        size_t ga = (size_t)(bm + r) * rowbytes + k0byte + c * 16;
        size_t gb = (size_t)(bn + r) * rowbytes + k0byte + c * 16;
        cp_async16(st + T_A + sw, Aw + ga);
        cp_async16(st + T_B + sw, Bw + gb);
    }
}

template <typename TOut>
__global__ __launch_bounds__(256, 2)
void gemm_fp16(const __half* __restrict__ Aw, const __half* __restrict__ Bw,
               const float* __restrict__ bias, TOut* __restrict__ C,
               int N, int K, int Klen, size_t zstride)
{
    extern __shared__ char smem[];
    const uint32_t sb = smem_to_u32(smem);
    const int tid = threadIdx.x;
    const int wid = tid >> 5, lid = tid & 31;
    const int wm = wid & 3, wn = wid >> 2;        // 4(m) x 2(n) warp grid
    const int bm = blockIdx.y * BM_;
    const int bn = blockIdx.x * BN_;
    const size_t rowbytes = (size_t)K * 2;
    const int NKC = Klen / BK_;
    const size_t kofs = (size_t)blockIdx.z * Klen * 2;

    const char* pA = (const char*)Aw + kofs;
    const char* pB = (const char*)Bw + kofs;
    C += (size_t)blockIdx.z * zstride;

    float acc[2][8][4];
#pragma unroll
    for (int mt = 0; mt < 2; mt++)
#pragma unroll
        for (int nt = 0; nt < 8; nt++)
#pragma unroll
            for (int j = 0; j < 4; j++) acc[mt][nt][j] = 0.0f;

    // Prologue: stages 0..4
#pragma unroll
    for (int s = 0; s < NSTAGE_ - 1; s++) {
        if (s < NKC) load_stage(sb + s * STG_, tid, pA, pB, rowbytes, bm, bn, s * BK_ * 2);
        cp_commit();
    }

#pragma unroll 1
    for (int kc = 0; kc < NKC; kc++) {
        cp_wait4();
        __syncthreads();
        {
            int nx = kc + NSTAGE_ - 1;
            if (nx < NKC)
                load_stage(sb + (nx % NSTAGE_) * STG_, tid, pA, pB, rowbytes, bm, bn, nx * BK_ * 2);
            cp_commit();
        }
        const uint32_t st = sb + (kc % NSTAGE_) * STG_;

#pragma unroll
        for (int kst = 0; kst < 2; kst++) {
            uint32_t af[2][4], bf[4][4];
#pragma unroll
            for (int mt = 0; mt < 2; mt++) {
                int row = wm * 32 + mt * 16 + (lid & 15);
                int lane = kst * 2 + (lid >> 4);
                ldsm_x4(af[mt], st + T_A + sw_off(row, lane));
            }
#pragma unroll
            for (int nt2 = 0; nt2 < 4; nt2++) {
                int row = wn * 64 + nt2 * 16 + (lid & 7) + ((lid >> 4) << 3);
                int lane = kst * 2 + ((lid >> 3) & 1);
                ldsm_x4(bf[nt2], st + T_B + sw_off(row, lane));
            }
#pragma unroll
            for (int mt = 0; mt < 2; mt++)
#pragma unroll
                for (int nt = 0; nt < 8; nt++)
                    mma_f16(acc[mt][nt], af[mt], &bf[nt >> 1][(nt & 1) * 2]);
        }
        __syncthreads();
    }

    // Epilogue: add bias (if any), store
    const int r0 = bm + wm * 32 + (lid >> 2);
    const int cq = (lid & 3) * 2;
#pragma unroll
    for (int mt = 0; mt < 2; mt++) {
#pragma unroll
        for (int nt = 0; nt < 8; nt++) {
            int col = bn + wn * 64 + nt * 8 + cq;
            float bx = 0.0f, by = 0.0f;
            if (bias) { bx = bias[col]; by = bias[col + 1]; }
            store2(C, (size_t)(r0 + mt * 16) * N + col,
                   acc[mt][nt][0] + bx, acc[mt][nt][1] + by);
            store2(C, (size_t)(r0 + mt * 16 + 8) * N + col,
                   acc[mt][nt][2] + bx, acc[mt][nt][3] + by);
        }
    }
}

// Split-K reduce: out[i] = p0[i] + p1[i] + bias[col]
__global__ void reduce_splitk(const float* __restrict__ part, const float* __restrict__ bias,
                              float* __restrict__ out, int n4, size_t zstride4, int Nmask4)
{
    int i = blockIdx.x * blockDim.x + threadIdx.x;
    if (i >= n4) return;
    float4 a = reinterpret_cast<const float4*>(part)[i];
    float4 b = reinterpret_cast<const float4*>(part)[i + zstride4];
    int col = (i & Nmask4) * 4;
    float4 v;
    v.x = a.x + b.x + bias[col + 0];
    v.y = a.y + b.y + bias[col + 1];
    v.z = a.z + b.z + bias[col + 2];
    v.w = a.w + b.w + bias[col + 3];
    reinterpret_cast<float4*>(out)[i] = v;
}

// ---------------------------------------------------------------------------
// Scan:  h_t = a*h_{t-1} + b_t, a = sigmoid(A[h]); chunked over L
// b is fp16; all accumulation in fp32.
// ---------------------------------------------------------------------------
__global__ void scan_reduceA(const __half* __restrict__ bbuf, const float* __restrict__ Araw,
                             float* __restrict__ carry)
{
    int idx = blockIdx.x * blockDim.x + threadIdx.x;   // [B, NC, H]
    int h = idx & (H_ - 1);
    int c = (idx >> 12) & (NC_ - 1);
    int bb = idx >> 16;
    float a = dsigmoid(Araw[h]);
    size_t base = ((size_t)bb * L_ + (size_t)c * CHUNK_) * H_ + h;
    float s = 0.0f;
#pragma unroll 8
    for (int i = 0; i < CHUNK_; i++)
        s = fmaf(a, s, __half2float(bbuf[base + (size_t)i * H_]));
    carry[idx] = s;
}

__global__ void scan_phaseB(const float* __restrict__ carry, const float* __restrict__ Araw,
                            float* __restrict__ hprev)
{
    int idx = blockIdx.x * blockDim.x + threadIdx.x;   // [B, H]
    int h = idx & (H_ - 1);
    int bb = idx >> 12;
    float a = dsigmoid(Araw[h]);
    float aC = a;
#pragma unroll
    for (int i = 0; i < 7; i++) aC *= aC;              // a^128
    float run = 0.0f;
#pragma unroll
    for (int c = 0; c < NC_; c++) {
        size_t off = ((size_t)bb * NC_ + c) * H_ + h;
        hprev[off] = run;
        run = fmaf(aC, run, carry[off]);
    }
}

__global__ void scan_phaseC(const __half* __restrict__ bbuf, const float* __restrict__ Araw,
                            const float* __restrict__ hprev,
                            __half* __restrict__ hh)
{
    int idx = blockIdx.x * blockDim.x + threadIdx.x;   // [B, NC, H]
    int h = idx & (H_ - 1);
    int c = (idx >> 12) & (NC_ - 1);
    int bb = idx >> 16;
    float a = dsigmoid(Araw[h]);
    float Hp = hprev[idx];
    size_t base = ((size_t)bb * L_ + (size_t)c * CHUNK_) * H_ + h;
    float s = 0.0f, p = 1.0f;
#pragma unroll 8
    for (int i = 0; i < CHUNK_; i++) {
        size_t off = base + (size_t)i * H_;
        p *= a;                                      // a^(i+1)
        s = fmaf(a, s, __half2float(bbuf[off]));     // local inclusive scan
        float v = fmaf(p, Hp, s);                    // + carry-in contribution
        hh[off] = __float2half_rn(v);
    }
}

// ---------------------------------------------------------------------------
extern "C" void kernel_launch(void* const* d_in, const int* in_sizes, int n_in,
                              void* d_out, int out_size)
{
    const float* x  = (const float*)d_in[0];   // [B, L, D]
    const float* WB = (const float*)d_in[1];   // [H, D]
    const float* bB = (const float*)d_in[2];   // [H]
    const float* WC = (const float*)d_in[3];   // [D, H]
    const float* bC = (const float*)d_in[4];   // [D]
    const float* A  = (const float*)d_in[5];   // [H]
    float* out = (float*)d_out;                // [B, L, D]

    float *arena, *carry, *hprev;
    __half *xh, *wbh, *wch, *hh;
    cudaGetSymbolAddress((void**)&arena, g_b);
    cudaGetSymbolAddress((void**)&carry, g_carry);
    cudaGetSymbolAddress((void**)&hprev, g_hprev);
    cudaGetSymbolAddress((void**)&xh, g_xh);
    cudaGetSymbolAddress((void**)&wbh, g_wbh);
    cudaGetSymbolAddress((void**)&wch, g_wch);
    cudaGetSymbolAddress((void**)&hh, g_hh);

    __half* bh = reinterpret_cast<__half*>(arena);        // front 64 MB: b fp16
    float* parts = arena + (size_t)16 * 1024 * 1024;      // back 64 MB: split-K partials

    const int SMEM_G = NSTAGE_ * STG_;     // 96 KB -> 2 CTAs/SM
    cudaFuncSetAttribute(gemm_fp16<__half>, cudaFuncAttributeMaxDynamicSharedMemorySize, SMEM_G);
    cudaFuncSetAttribute(gemm_fp16<float>, cudaFuncAttributeMaxDynamicSharedMemorySize, SMEM_G);

    // Convert inputs to fp16
    conv_f32_h<<<(M_ * D_ / 4 + 255) / 256, 256>>>(x, xh, M_ * D_ / 4);
    conv_f32_h<<<(H_ * D_ / 4 + 255) / 256, 256>>>(WB, wbh, H_ * D_ / 4);
    conv_f32_h<<<(D_ * H_ / 4 + 255) / 256, 256>>>(WC, wch, D_ * H_ / 4);

    // GEMM1: b = x @ WB^T + bB   (M=8192, N=4096, K=256), fp16 output
    gemm_fp16<__half><<<dim3(H_ / BN_, M_ / BM_, 1), 256, SMEM_G>>>(
        xh, wbh, bB, bh, H_, D_, D_, 0);

    // Scan over L
    scan_reduceA<<<(B_ * NC_ * H_) / 256, 256>>>(bh, A, carry);
    scan_phaseB<<<(B_ * H_) / 256, 256>>>(carry, A, hprev);
    scan_phaseC<<<(B_ * NC_ * H_) / 256, 256>>>(bh, A, hprev, hh);

    // GEMM2: out = h @ WC^T + bC  (M=8192, N=256, K=4096), split-K=2.
    const size_t zstride = (size_t)M_ * D_;
    gemm_fp16<float><<<dim3(D_ / BN_, M_ / BM_, 2), 256, SMEM_G>>>(
        hh, wch, nullptr, parts, D_, H_, H_ / 2, zstride);
    reduce_splitk<<<(M_ * D_ / 4 + 255) / 256, 256>>>(
        parts, bC, out, M_ * D_ / 4, zstride / 4, (D_ / 4) - 1);
}